// round 8
// baseline (speedup 1.0000x reference)
#include <cuda_runtime.h>
#include <cuda_fp16.h>
#include <cstdint>
#include <cstring>

// Problem dims (fixed by setup_inputs)
constexpr int Bd = 4;
constexpr int Sd = 2048;
constexpr int Ed = 1024;
constexpr float SCALE_F = 0.125f;

// ===========================================================================
// scratch layout (bytes) — all split matrices are fp16 hi/lo limb pairs
// ===========================================================================
constexpr long MB = 1024 * 1024;
constexpr long OFF_XS_H = 0;          // x split      [B][S][E]  16MB
constexpr long OFF_XS_L = 16 * MB;
constexpr long OFF_XT_H = 32 * MB;    // x^T split    [B][E][S]  16MB
constexpr long OFF_XT_L = 48 * MB;
constexpr long OFF_WQT_H = 64 * MB;   // Wq^T split   [E][E]      2MB
constexpr long OFF_WQT_L = 66 * MB;
constexpr long OFF_WKT_H = 68 * MB;
constexpr long OFF_WKT_L = 70 * MB;
constexpr long OFF_WVT_H = 72 * MB;
constexpr long OFF_WVT_L = 74 * MB;
constexpr long OFF_WO_H  = 76 * MB;   // Wo split (no transpose)
constexpr long OFF_WO_L  = 78 * MB;
constexpr long OFF_P_H   = 80 * MB;   // P = Wq^T Wk
constexpr long OFF_P_L   = 82 * MB;
constexpr long OFF_Q_H   = 84 * MB;   // Q = Wo Wv
constexpr long OFF_Q_L   = 86 * MB;
constexpr long OFF_G_H   = 88 * MB;   // G  [B][E][E]  8MB
constexpr long OFF_G_L   = 96 * MB;
constexpr long OFF_R_H   = 104 * MB;  // R = Q G
constexpr long OFF_R_L   = 112 * MB;
constexpr long OFF_UT_H  = 120 * MB;  // U^T
constexpr long OFF_UT_L  = 128 * MB;
constexpr long OFF_VEC   = 136 * MB;  // fp32 vectors
constexpr long SCRATCH_BYTES = 138 * MB;

__device__ __align__(1024) char g_scratch[SCRATCH_BYTES];

// ===========================================================================
// helpers
// ===========================================================================
__device__ __forceinline__ uint32_t smem_u32(const void* p) {
    uint32_t a;
    asm("{ .reg .u64 t; cvta.to.shared.u64 t, %1; cvt.u32.u64 %0, t; }" : "=r"(a) : "l"(p));
    return a;
}
#define SWZ128(o) ((o) ^ (((o) >> 3) & 0x70))

__device__ __forceinline__ void split1(float v, float& h, float& l) {
    h = __half2float(__float2half_rn(v));
    l = v - h;
}
__device__ __forceinline__ uint32_t pack2(float a, float b) {
    __half ha = __float2half_rn(a), hb = __float2half_rn(b);
    uint16_t ua, ub;
    memcpy(&ua, &ha, 2); memcpy(&ub, &hb, 2);
    return (uint32_t)ua | ((uint32_t)ub << 16);
}

#define LDMX4(r0, r1, r2, r3, addr)                                            \
    asm volatile("ldmatrix.sync.aligned.m8n8.x4.shared.b16 {%0,%1,%2,%3}, [%4];" \
                 : "=r"(r0), "=r"(r1), "=r"(r2), "=r"(r3) : "r"(addr))

__device__ __forceinline__ void mma16816(float* c, const uint32_t* a, const uint32_t* b) {
    asm volatile(
        "mma.sync.aligned.m16n8k16.row.col.f32.f16.f16.f32 "
        "{%0,%1,%2,%3},{%4,%5,%6,%7},{%8,%9},{%0,%1,%2,%3};"
        : "+f"(c[0]), "+f"(c[1]), "+f"(c[2]), "+f"(c[3])
        : "r"(a[0]), "r"(a[1]), "r"(a[2]), "r"(a[3]), "r"(b[0]), "r"(b[1]));
}
__device__ __forceinline__ void cp16(uint32_t dst, const void* src) {
    asm volatile("cp.async.cg.shared.global [%0], [%1], 16;" :: "r"(dst), "l"(src));
}

// ===========================================================================
// preprocessing: fp32 -> fp16 hi/lo (elementwise + transposed)
// ===========================================================================
__global__ void split_k(const float* __restrict__ in,
                        __half* __restrict__ oh,
                        __half* __restrict__ ol, long n4) {
    long i = (long)blockIdx.x * blockDim.x + threadIdx.x;
    if (i >= n4) return;
    float4 v = ((const float4*)in)[i];
    float h0, l0, h1, l1, h2, l2, h3, l3;
    split1(v.x, h0, l0); split1(v.y, h1, l1);
    split1(v.z, h2, l2); split1(v.w, h3, l3);
    ((uint2*)oh)[i] = make_uint2(pack2(h0, h1), pack2(h2, h3));
    ((uint2*)ol)[i] = make_uint2(pack2(l0, l1), pack2(l2, l3));
}

// in: [R][C] fp32 (batch z, stride sIn elems) -> out: [C][R] fp16 hi/lo
__global__ void tsplit_k(const float* __restrict__ in, long sIn,
                         __half* __restrict__ oh,
                         __half* __restrict__ ol, long sOut,
                         int R, int C) {
    __shared__ float t[32][33];
    in += (long)blockIdx.z * sIn;
    oh += (long)blockIdx.z * sOut;
    ol += (long)blockIdx.z * sOut;
    int c0 = blockIdx.x * 32, r0 = blockIdx.y * 32;
    int tx = threadIdx.x, ty = threadIdx.y;  // (32,8)
#pragma unroll
    for (int i = 0; i < 4; i++)
        t[ty + i * 8][tx] = in[(long)(r0 + ty + i * 8) * C + c0 + tx];
    __syncthreads();
#pragma unroll
    for (int i = 0; i < 4; i++) {
        float v = t[tx][ty + i * 8];
        float h, l;
        split1(v, h, l);
        long o = (long)(c0 + ty + i * 8) * R + r0 + tx;
        oh[o] = __float2half_rn(h);
        ol[o] = __float2half_rn(l);
    }
}

// mirror upper-triangle tiles of symmetric fp16 matrix into lower triangle
__global__ void mirror_k(__half* __restrict__ Gh,
                         __half* __restrict__ Gl, long sEE) {
    int bi = blockIdx.y, bj = blockIdx.x;
    if (bi > bj) return;
    __half* G = ((blockIdx.z & 1) ? Gl : Gh) + (long)(blockIdx.z >> 1) * sEE;
    __shared__ uint16_t t[32][33];
    int tx = threadIdx.x, ty = threadIdx.y;
    int r0 = bi * 32, c0 = bj * 32;
#pragma unroll
    for (int i = 0; i < 4; i++) {
        int r = ty + i * 8;
        uint16_t v;
        memcpy(&v, &G[(long)(r0 + r) * Ed + c0 + tx], 2);
        t[r][tx] = v;
    }
    __syncthreads();
#pragma unroll
    for (int i = 0; i < 4; i++) {
        int rr = ty + i * 8;
        int cc = tx;
        int dr = c0 + rr, dc = r0 + cc;
        if (dr > dc) {
            uint16_t v = t[cc][rr];
            memcpy(&G[(long)dr * Ed + dc], &v, 2);
        }
    }
}

// ===========================================================================
// small vector kernels (fp32)
// ===========================================================================
__global__ void coldot_k(const float* __restrict__ A, long sA,
                         const float* __restrict__ w, long sw,
                         float* __restrict__ y, int sy, int rows, int ldr) {
    A += (long)blockIdx.y * sA;
    if (w) w += (long)blockIdx.y * sw;
    y += blockIdx.y * sy;
    int j = blockIdx.x * blockDim.x + threadIdx.x;
    float acc = 0.f;
#pragma unroll 8
    for (int i = 0; i < rows; i++) {
        float wv = w ? w[i] : 1.f;
        acc += A[(long)i * ldr + j] * wv;
    }
    y[j] = acc;
}

// z=0: y=u2=Wq^T bk ; z=1: y=t1=Wk^T bq
__global__ void coldot2_k(const float* __restrict__ Wq, const float* __restrict__ bk,
                          const float* __restrict__ Wk, const float* __restrict__ bq,
                          float* __restrict__ u2, float* __restrict__ t1) {
    const float* A = blockIdx.z ? Wk : Wq;
    const float* w = blockIdx.z ? bq : bk;
    float* y = blockIdx.z ? t1 : u2;
    int j = blockIdx.x * blockDim.x + threadIdx.x;
    float acc = 0.f;
#pragma unroll 8
    for (int i = 0; i < Ed; i++) acc += A[(long)i * Ed + j] * w[i];
    y[j] = acc;
}

__global__ void rowdot_k(const float* __restrict__ A,
                         const float* __restrict__ xv, int sxv,
                         const float* __restrict__ bias,
                         float* __restrict__ y, int sy, int cols, float alpha) {
    xv += blockIdx.y * sxv;
    y  += blockIdx.y * sy;
    int warp = blockIdx.x * (blockDim.x >> 5) + (threadIdx.x >> 5);
    int lane = threadIdx.x & 31;
    const float* row = A + (long)warp * cols;
    float acc = 0.f;
    for (int j = lane; j < cols; j += 32) acc += row[j] * xv[j];
#pragma unroll
    for (int o = 16; o > 0; o >>= 1) acc += __shfl_xor_sync(0xffffffffu, acc, o);
    if (lane == 0) y[warp] = alpha * acc + (bias ? bias[warp] : 0.f);
}

// z=0: p_b = Wk s_b ; z=1: r_b = Wv s_b
__global__ void rowdot_pr_k(const float* __restrict__ Wk, const float* __restrict__ Wv,
                            const float* __restrict__ s,
                            float* __restrict__ p, float* __restrict__ r) {
    const float* A = blockIdx.z ? Wv : Wk;
    float* y = (blockIdx.z ? r : p) + blockIdx.y * Ed;
    const float* xv = s + blockIdx.y * Ed;
    int warp = blockIdx.x * 8 + (threadIdx.x >> 5);
    int lane = threadIdx.x & 31;
    const float* row = A + (long)warp * Ed;
    float acc = 0.f;
    for (int j = lane; j < Ed; j += 32) acc += row[j] * xv[j];
#pragma unroll
    for (int o = 16; o > 0; o >>= 1) acc += __shfl_xor_sync(0xffffffffu, acc, o);
    if (lane == 0) y[warp] = acc;
}

// y_b[i] = dot((Ah+Al)[i,:], xv)  over split fp16 matrix (batched)
__global__ void rowdot_hf2_k(const __half* __restrict__ Ah,
                             const __half* __restrict__ Al, long sA,
                             const float* __restrict__ xv,
                             float* __restrict__ y, int sy, int cols) {
    Ah += (long)blockIdx.y * sA;
    Al += (long)blockIdx.y * sA;
    y  += blockIdx.y * sy;
    int warp = blockIdx.x * (blockDim.x >> 5) + (threadIdx.x >> 5);
    int lane = threadIdx.x & 31;
    const __half* rh = Ah + (long)warp * cols;
    const __half* rl = Al + (long)warp * cols;
    float acc = 0.f;
    for (int j = lane; j < cols; j += 32)
        acc += (__half2float(rh[j]) + __half2float(rl[j])) * xv[j];
#pragma unroll
    for (int o = 16; o > 0; o >>= 1) acc += __shfl_xor_sync(0xffffffffu, acc, o);
    if (lane == 0) y[warp] = acc;
}

// blocks 0..Bd-1: dp[b] = p_b . bq ; block Bd: db = bk . bq
__global__ void dot2_k(const float* __restrict__ p, const float* __restrict__ bk,
                       const float* __restrict__ bq,
                       float* __restrict__ dp, float* __restrict__ db) {
    int bid = blockIdx.x;
    const float* a = (bid < Bd) ? p + (long)bid * Ed : bk;
    __shared__ float red[8];
    int tid = threadIdx.x;
    float acc = 0.f;
    for (int j = tid; j < Ed; j += 256) acc += a[j] * bq[j];
#pragma unroll
    for (int o = 16; o > 0; o >>= 1) acc += __shfl_xor_sync(0xffffffffu, acc, o);
    if ((tid & 31) == 0) red[tid >> 5] = acc;
    __syncthreads();
    if (tid < 8) {
        float v = red[tid];
#pragma unroll
        for (int o = 4; o > 0; o >>= 1) v += __shfl_xor_sync(0xffu, v, o);
        if (tid == 0) { if (bid < Bd) dp[bid] = v; else db[0] = v; }
    }
}

// d_b[i] = wvt2_b[i] + bv[i]*(dp[b] + S*db) + r_b[i]*db
__global__ void vfin_k(float* __restrict__ d, const float* __restrict__ wvt2,
                       const float* __restrict__ bv, const float* __restrict__ r,
                       const float* __restrict__ dp, const float* __restrict__ db) {
    int b = blockIdx.y;
    int i = blockIdx.x * 256 + threadIdx.x;
    float dbv = db[0];
    d[(long)b * Ed + i] = wvt2[(long)b * Ed + i]
                        + bv[i] * (dp[b] + (float)Sd * dbv)
                        + r[(long)b * Ed + i] * dbv;
}

// ===========================================================================
// fp16 2-product split GEMM engine (unchanged from R7)
// ===========================================================================
constexpr int OFF_A  = 0;
constexpr int OFF_BH = 16384;
constexpr int OFF_BL = 32768;
constexpr int STAGE  = 49152;
constexpr int DYN_SMEM = 4 * STAGE;  // 192 KB

__device__ __forceinline__ void issue_tile(uint32_t sdst, const __half* g,
                                           long ldK, int tid) {
#pragma unroll
    for (int i = 0; i < 2; i++) {
        int gi = tid + i * 512;
        int row = gi >> 3, c16 = gi & 7;
        uint32_t off = SWZ128((uint32_t)(row * 128 + c16 * 16));
        cp16(sdst + off, (const char*)(g + (long)row * ldK) + c16 * 16);
    }
}

__device__ __forceinline__ void compute_ks(uint32_t sb, int ks, int mw, int nw,
                                           int lane, float (&acc)[2][4][4]) {
    const uint32_t rowsel = lane & 15;
    const uint32_t ksel = (lane >> 4) * 16;
    uint32_t ah[2][4];
#pragma unroll
    for (int mt = 0; mt < 2; mt++) {
        uint32_t off = SWZ128((uint32_t)((mw + mt * 16 + rowsel) * 128 + ks * 32 + ksel));
        LDMX4(ah[mt][0], ah[mt][1], ah[mt][2], ah[mt][3], sb + OFF_A + off);
    }
    uint32_t bh[4][2], bl[4][2];
#pragma unroll
    for (int nt = 0; nt < 2; nt++) {
        uint32_t off = SWZ128((uint32_t)((nw + nt * 16 + rowsel) * 128 + ks * 32 + ksel));
        uint32_t r0, r1, r2, r3;
        LDMX4(r0, r1, r2, r3, sb + OFF_BH + off);
        bh[2 * nt][0] = r0; bh[2 * nt][1] = r2;
        bh[2 * nt + 1][0] = r1; bh[2 * nt + 1][1] = r3;
        LDMX4(r0, r1, r2, r3, sb + OFF_BL + off);
        bl[2 * nt][0] = r0; bl[2 * nt][1] = r2;
        bl[2 * nt + 1][0] = r1; bl[2 * nt + 1][1] = r3;
    }
#pragma unroll
    for (int mt = 0; mt < 2; mt++)
#pragma unroll
        for (int nf = 0; nf < 4; nf++) {
            mma16816(acc[mt][nf], ah[mt], bh[nf]);  // hi*hi
            mma16816(acc[mt][nf], ah[mt], bl[nf]);  // hi*lo
        }
}

__global__ void __launch_bounds__(512, 1) hf_gemm(
    const __half* __restrict__ Ah, long sA,
    const __half* __restrict__ Bh, const __half* __restrict__ Bl, long sB,
    float* __restrict__ Cf, long sCf,
    __half* __restrict__ Ch, __half* __restrict__ Cl, long sCb,
    int Nd, int Kd, float alpha, int mode, int tri, int dual,
    const __half* __restrict__ A2h, const __half* __restrict__ B2h,
    const __half* __restrict__ B2l, __half* __restrict__ C2h, __half* __restrict__ C2l,
    const float* __restrict__ v1, int sv1, const float* __restrict__ v2,
    const float* __restrict__ v3, const float* __restrict__ v4, int sv4, float rk)
{
    extern __shared__ char smem[];
    const int bz = blockIdx.z;
    if (dual && bz == 1) {
        Ah = A2h; Bh = B2h; Bl = B2l; Ch = C2h; Cl = C2l;
    } else {
        Ah += (long)bz * sA;
        Bh += (long)bz * sB; Bl += (long)bz * sB;
        if (Cf) Cf += (long)bz * sCf;
        if (Ch) { Ch += (long)bz * sCb; Cl += (long)bz * sCb; }
        if (v1) v1 += (long)bz * sv1;
        if (v4) v4 += (long)bz * sv4;
    }

    int m0, n0;
    if (tri) {
        int t = blockIdx.x, ti = 0;
        while (t >= 8 - ti) { t -= 8 - ti; ti++; }
        m0 = ti * 128;
        n0 = (ti + t) * 128;
    } else {
        m0 = blockIdx.y * 128;
        n0 = blockIdx.x * 128;
    }
    const int tid = threadIdx.x;
    const int wid = tid >> 5;
    const int lane = tid & 31;
    const int mw = (wid >> 2) * 32;
    const int nw = (wid & 3) * 32;
    const uint32_t sbase = smem_u32(smem);

    float acc[2][4][4];
#pragma unroll
    for (int mt = 0; mt < 2; mt++)
#pragma unroll
        for (int nf = 0; nf < 4; nf++)
#pragma unroll
            for (int q = 0; q < 4; q++) acc[mt][nf][q] = 0.f;

    const int nCh = Kd / 64;
    auto issue = [&](int c) {
        uint32_t sb = sbase + (uint32_t)(c & 3) * STAGE;
        long k0 = (long)c * 64;
        issue_tile(sb + OFF_A,  Ah + (long)m0 * Kd + k0, Kd, tid);
        issue_tile(sb + OFF_BH, Bh + (long)n0 * Kd + k0, Kd, tid);
        issue_tile(sb + OFF_BL, Bl + (long)n0 * Kd + k0, Kd, tid);
        asm volatile("cp.async.commit_group;" ::: "memory");
    };

    issue(0); issue(1); issue(2);
    for (int c = 0; c < nCh; c++) {
        if (c + 3 <= nCh) {
            asm volatile("cp.async.wait_group 2;" ::: "memory");
        } else if (c + 2 == nCh) {
            asm volatile("cp.async.wait_group 1;" ::: "memory");
        } else {
            asm volatile("cp.async.wait_group 0;" ::: "memory");
        }
        __syncthreads();
        if (c + 3 < nCh) issue(c + 3);
        const uint32_t sb = sbase + (uint32_t)(c & 3) * STAGE;
        compute_ks(sb, 0, mw, nw, lane, acc);
        compute_ks(sb, 1, mw, nw, lane, acc);
        compute_ks(sb, 2, mw, nw, lane, acc);
        compute_ks(sb, 3, mw, nw, lane, acc);
    }
    __syncthreads();

    // epilogue
    const int r = lane >> 2;
    const int cp = (lane & 3) * 2;
#pragma unroll
    for (int mt = 0; mt < 2; mt++)
#pragma unroll
        for (int rr = 0; rr < 2; rr++) {
            const int m = m0 + mw + mt * 16 + r + rr * 8;
            float pv = 0.f, bkv = 0.f;
            if (mode == 1) { pv = v1[m]; bkv = v3[m]; }
#pragma unroll
            for (int nf = 0; nf < 4; nf++) {
                const int nloc = nf * 8 + cp;
                const int n = n0 + nw + nloc;
                float f0 = alpha * acc[mt][nf][rr * 2 + 0];
                float f1 = alpha * acc[mt][nf][rr * 2 + 1];
                if (mode == 1) {
                    f0 += pv * v2[n + 0] + bkv * (v4[n + 0] + rk * v2[n + 0]);
                    f1 += pv * v2[n + 1] + bkv * (v4[n + 1] + rk * v2[n + 1]);
                } else if (mode == 2) {
                    f0 += v1[n + 0];
                    f1 += v1[n + 1];
                }
                long co = (long)m * Nd + n;
                if (Cf) *(float2*)(Cf + co) = make_float2(f0, f1);
                if (Ch) {
                    float h0, l0, h1, l1;
                    split1(f0, h0, l0);
                    split1(f1, h1, l1);
                    *(uint32_t*)(Ch + co) = pack2(h0, h1);
                    *(uint32_t*)(Cl + co) = pack2(l0, l1);
                }
            }
        }
}

// ===========================================================================
// Launch — two-stream fork/join (graph-capture-safe event wiring).
//   s0 (critical): tsplit(x) -> G(tri) -> mirror -> [wait PQ] -> R -> UT
//                  -> [wait cb] -> out
//   s1 (overlap):  splits, vector chain, P/Q dual GEMM -> evPQ ;
//                  [wait G] -> t2 -> wvt2 -> d -> cb -> evCB
// ===========================================================================
static cudaStream_t g_s1 = nullptr;
static cudaEvent_t g_evFork = nullptr, g_evG = nullptr, g_evPQ = nullptr, g_evCB = nullptr;

extern "C" void kernel_launch(void* const* d_in, const int* in_sizes, int n_in,
                              void* d_out, int out_size)
{
    const float* x  = (const float*)d_in[0];
    const float* Wq = (const float*)d_in[1];
    const float* bq = (const float*)d_in[2];
    const float* Wk = (const float*)d_in[3];
    const float* bk = (const float*)d_in[4];
    const float* Wv = (const float*)d_in[5];
    const float* bv = (const float*)d_in[6];
    const float* Wo = (const float*)d_in[7];
    const float* bo = (const float*)d_in[8];
    float* out = (float*)d_out;

    if (!g_s1) {
        cudaStreamCreateWithFlags(&g_s1, cudaStreamNonBlocking);
        cudaEventCreateWithFlags(&g_evFork, cudaEventDisableTiming);
        cudaEventCreateWithFlags(&g_evG,    cudaEventDisableTiming);
        cudaEventCreateWithFlags(&g_evPQ,   cudaEventDisableTiming);
        cudaEventCreateWithFlags(&g_evCB,   cudaEventDisableTiming);
    }
    cudaStream_t s0 = 0;       // harness capture stream (legacy default)
    cudaStream_t s1 = g_s1;

    char* scr = nullptr;
    cudaGetSymbolAddress((void**)&scr, g_scratch);
    auto HF = [&](long off) { return (__half*)(scr + off); };

    __half *xs_h = HF(OFF_XS_H), *xs_l = HF(OFF_XS_L);
    __half *xt_h = HF(OFF_XT_H), *xt_l = HF(OFF_XT_L);
    __half *wqt_h = HF(OFF_WQT_H), *wqt_l = HF(OFF_WQT_L);
    __half *wkt_h = HF(OFF_WKT_H), *wkt_l = HF(OFF_WKT_L);
    __half *wvt_h = HF(OFF_WVT_H), *wvt_l = HF(OFF_WVT_L);
    __half *wo_h  = HF(OFF_WO_H),  *wo_l  = HF(OFF_WO_L);
    __half *P_h = HF(OFF_P_H), *P_l = HF(OFF_P_L);
    __half *Q_h = HF(OFF_Q_H), *Q_l = HF(OFF_Q_L);
    __half *G_h = HF(OFF_G_H), *G_l = HF(OFF_G_L);
    __half *R_h = HF(OFF_R_H), *R_l = HF(OFF_R_L);
    __half *UT_h = HF(OFF_UT_H), *UT_l = HF(OFF_UT_L);

    float* vec = (float*)(scr + OFF_VEC);
    float* s    = vec;                 // [B][E]
    float* p    = s    + Bd * Ed;
    float* r    = p    + Bd * Ed;
    float* u1   = r    + Bd * Ed;
    float* w2   = u1   + Bd * Ed;
    float* t2   = w2   + Bd * Ed;
    float* wvt2 = t2   + Bd * Ed;
    float* d    = wvt2 + Bd * Ed;
    float* cb   = d    + Bd * Ed;
    float* u2   = cb   + Bd * Ed;      // [E]
    float* w1   = u2   + Ed;
    float* t1   = w1   + Ed;
    float* dp   = t1   + Ed;           // [B]
    float* db   = dp   + Bd;           // [1]

    const long sX = (long)Sd * Ed;     // 2M elems
    const long sXT = (long)Ed * Sd;
    const long sEE = (long)Ed * Ed;

    cudaFuncSetAttribute(hf_gemm, cudaFuncAttributeMaxDynamicSharedMemorySize, DYN_SMEM);

    dim3 blk(512);

    // ---- fork ----
    cudaEventRecord(g_evFork, s0);
    cudaStreamWaitEvent(s1, g_evFork, 0);

    // ==== s1: preprocessing (except tsplit x), vector chain, P/Q GEMM ====
    split_k<<<(Bd * sX / 4 + 255) / 256, 256, 0, s1>>>(x, xs_h, xs_l, Bd * sX / 4);
    split_k<<<(sEE / 4 + 255) / 256, 256, 0, s1>>>(Wo, wo_h, wo_l, sEE / 4);
    tsplit_k<<<dim3(Ed / 32, Ed / 32, 1), dim3(32, 8), 0, s1>>>(Wq, 0, wqt_h, wqt_l, 0, Ed, Ed);
    tsplit_k<<<dim3(Ed / 32, Ed / 32, 1), dim3(32, 8), 0, s1>>>(Wk, 0, wkt_h, wkt_l, 0, Ed, Ed);
    tsplit_k<<<dim3(Ed / 32, Ed / 32, 1), dim3(32, 8), 0, s1>>>(Wv, 0, wvt_h, wvt_l, 0, Ed, Ed);

    coldot_k<<<dim3(Ed / 256, Bd), 256, 0, s1>>>(x, sX, nullptr, 0, s, Ed, Sd, Ed);
    rowdot_pr_k<<<dim3(Ed / 8, Bd, 2), 256, 0, s1>>>(Wk, Wv, s, p, r);
    coldot_k<<<dim3(Ed / 256, Bd), 256, 0, s1>>>(Wq, 0, p, Ed, u1, Ed, Ed, Ed);
    coldot2_k<<<dim3(Ed / 256, 1, 2), 256, 0, s1>>>(Wq, bk, Wk, bq, u2, t1);
    rowdot_k<<<dim3(Ed / 8, 1), 256, 0, s1>>>(Wo, bv, 0, nullptr, w1, 0, Ed, 1.f);
    rowdot_k<<<dim3(Ed / 8, Bd), 256, 0, s1>>>(Wo, r, Ed, nullptr, w2, Ed, Ed, 1.f);
    dot2_k<<<Bd + 1, 256, 0, s1>>>(p, bk, bq, dp, db);

    // merged: z=0 -> P = Wq^T Wk ; z=1 -> Q = Wo Wv
    hf_gemm<<<dim3(8, 8, 2), blk, DYN_SMEM, s1>>>(wqt_h, 0, wkt_h, wkt_l, 0,
        nullptr, 0, P_h, P_l, 0, Ed, Ed, 1.f, 0, 0, 1,
        wo_h, wvt_h, wvt_l, Q_h, Q_l,
        nullptr, 0, nullptr, nullptr, nullptr, 0, 0.f);
    cudaEventRecord(g_evPQ, s1);

    // ==== s0: critical path ====
    tsplit_k<<<dim3(Ed / 32, Sd / 32, Bd), dim3(32, 8), 0, s0>>>(x, sX, xt_h, xt_l, sXT, Sd, Ed);
    // G_b = x^T x : upper-triangle tiles (36) per batch, K=S
    hf_gemm<<<dim3(36, 1, Bd), blk, DYN_SMEM, s0>>>(xt_h, sXT, xt_h, xt_l, sXT,
        nullptr, 0, G_h, G_l, sEE, Ed, Sd, 1.f, 0, 1, 0,
        nullptr, nullptr, nullptr, nullptr, nullptr,
        nullptr, 0, nullptr, nullptr, nullptr, 0, 0.f);
    mirror_k<<<dim3(Ed / 32, Ed / 32, Bd * 2), dim3(32, 8), 0, s0>>>(G_h, G_l, sEE);
    cudaEventRecord(g_evG, s0);

    // ==== s1: cb chain (needs G from s0 + vectors local to s1) ====
    cudaStreamWaitEvent(s1, g_evG, 0);
    rowdot_hf2_k<<<dim3(Ed / 8, Bd), 256, 0, s1>>>(G_h, G_l, sEE, t1, t2, Ed, Ed);
    rowdot_k<<<dim3(Ed / 8, Bd), 256, 0, s1>>>(Wv, t2, Ed, nullptr, wvt2, Ed, Ed, 1.f);
    vfin_k<<<dim3(Ed / 256, Bd), 256, 0, s1>>>(d, wvt2, bv, r, dp, db);
    rowdot_k<<<dim3(Ed / 8, Bd), 256, 0, s1>>>(Wo, d, Ed, bo, cb, Ed, Ed, SCALE_F);
    cudaEventRecord(g_evCB, s1);

    // ==== s0: R, UT (need P/Q + vectors from s1) ====
    cudaStreamWaitEvent(s0, g_evPQ, 0);
    // R_b = Q G_b (G symmetric -> row-major as B ok)
    hf_gemm<<<dim3(8, 8, Bd), blk, DYN_SMEM, s0>>>(Q_h, 0, G_h, G_l, sEE,
        nullptr, 0, R_h, R_l, sEE, Ed, Ed, 1.f, 0, 0, 0,
        nullptr, nullptr, nullptr, nullptr, nullptr,
        nullptr, 0, nullptr, nullptr, nullptr, 0, 0.f);
    // UT_b = R_b P^T + w2 u2^T + w1 (u1 + S u2)^T
    hf_gemm<<<dim3(8, 8, Bd), blk, DYN_SMEM, s0>>>(R_h, sEE, P_h, P_l, 0,
        nullptr, 0, UT_h, UT_l, sEE, Ed, Ed, 1.f, 1, 0, 0,
        nullptr, nullptr, nullptr, nullptr, nullptr,
        w2, Ed, u2, w1, u1, Ed, (float)Sd);

    // ==== join: out needs cb (s1) ====
    cudaStreamWaitEvent(s0, g_evCB, 0);
    // out_b = SCALE * x UT^T + c_b
    hf_gemm<<<dim3(8, 16, Bd), blk, DYN_SMEM, s0>>>(xs_h, sX, UT_h, UT_l, sEE,
        out, sX, nullptr, nullptr, 0, Ed, Ed, SCALE_F, 2, 0, 0,
        nullptr, nullptr, nullptr, nullptr, nullptr,
        cb, Ed, nullptr, nullptr, nullptr, 0, 0.f);
}

// round 9
// speedup vs baseline: 1.0551x; 1.0551x over previous
#include <cuda_runtime.h>
#include <cuda_fp16.h>
#include <cstdint>
#include <cstring>

// Problem dims (fixed by setup_inputs)
constexpr int Bd = 4;
constexpr int Sd = 2048;
constexpr int Ed = 1024;
constexpr float SCALE_F = 0.125f;

// ===========================================================================
// scratch layout (bytes) — fp16 limb arrays (lo omitted where never read)
// ===========================================================================
constexpr long MB = 1024 * 1024;
constexpr long OFF_XS_H = 0;          // x split hi   [B][S][E]  16MB
constexpr long OFF_XT_H = 32 * MB;    // x^T split    [B][E][S]  16MB
constexpr long OFF_XT_L = 48 * MB;
constexpr long OFF_WQT_H = 64 * MB;   // Wq^T hi      [E][E]      2MB
constexpr long OFF_WKT_H = 68 * MB;
constexpr long OFF_WKT_L = 70 * MB;
constexpr long OFF_WVT_H = 72 * MB;
constexpr long OFF_WVT_L = 74 * MB;
constexpr long OFF_WO_H  = 76 * MB;   // Wo hi (no transpose)
constexpr long OFF_P_H   = 80 * MB;   // P = Wq^T Wk (both limbs)
constexpr long OFF_P_L   = 82 * MB;
constexpr long OFF_Q_H   = 84 * MB;   // Q = Wo Wv (hi only)
constexpr long OFF_G_H   = 88 * MB;   // G  [B][E][E]  8MB
constexpr long OFF_G_L   = 96 * MB;
constexpr long OFF_R_H   = 104 * MB;  // R = Q G (hi only)
constexpr long OFF_UT_H  = 120 * MB;  // U^T (both limbs)
constexpr long OFF_UT_L  = 128 * MB;
constexpr long OFF_VEC   = 136 * MB;  // fp32 vectors
constexpr long SCRATCH_BYTES = 138 * MB;

__device__ __align__(1024) char g_scratch[SCRATCH_BYTES];

// ===========================================================================
// helpers
// ===========================================================================
__device__ __forceinline__ uint32_t smem_u32(const void* p) {
    uint32_t a;
    asm("{ .reg .u64 t; cvta.to.shared.u64 t, %1; cvt.u32.u64 %0, t; }" : "=r"(a) : "l"(p));
    return a;
}
#define SWZ128(o) ((o) ^ (((o) >> 3) & 0x70))

__device__ __forceinline__ void split1(float v, float& h, float& l) {
    h = __half2float(__float2half_rn(v));
    l = v - h;
}
__device__ __forceinline__ uint32_t pack2(float a, float b) {
    __half ha = __float2half_rn(a), hb = __float2half_rn(b);
    uint16_t ua, ub;
    memcpy(&ua, &ha, 2); memcpy(&ub, &hb, 2);
    return (uint32_t)ua | ((uint32_t)ub << 16);
}

#define LDMX4(r0, r1, r2, r3, addr)                                            \
    asm volatile("ldmatrix.sync.aligned.m8n8.x4.shared.b16 {%0,%1,%2,%3}, [%4];" \
                 : "=r"(r0), "=r"(r1), "=r"(r2), "=r"(r3) : "r"(addr))

__device__ __forceinline__ void mma16816(float* c, const uint32_t* a, const uint32_t* b) {
    asm volatile(
        "mma.sync.aligned.m16n8k16.row.col.f32.f16.f16.f32 "
        "{%0,%1,%2,%3},{%4,%5,%6,%7},{%8,%9},{%0,%1,%2,%3};"
        : "+f"(c[0]), "+f"(c[1]), "+f"(c[2]), "+f"(c[3])
        : "r"(a[0]), "r"(a[1]), "r"(a[2]), "r"(a[3]), "r"(b[0]), "r"(b[1]));
}
__device__ __forceinline__ void cp16(uint32_t dst, const void* src) {
    asm volatile("cp.async.cg.shared.global [%0], [%1], 16;" :: "r"(dst), "l"(src));
}

// ===========================================================================
// preprocessing
// ===========================================================================
// y=0: x -> xs_h (hi only) ; y=1: Wo -> wo_h (hi only)
__global__ void split_hi2_k(const float* __restrict__ x, __half* __restrict__ xs_h, long n4x,
                            const float* __restrict__ Wo, __half* __restrict__ wo_h, long n4w) {
    long i = (long)blockIdx.x * blockDim.x + threadIdx.x;
    const float* in; __half* oh; long n4;
    if (blockIdx.y == 0) { in = x; oh = xs_h; n4 = n4x; }
    else                 { in = Wo; oh = wo_h; n4 = n4w; }
    if (i >= n4) return;
    float4 v = ((const float4*)in)[i];
    ((uint2*)oh)[i] = make_uint2(pack2(__half2float(__float2half_rn(v.x)),
                                       __half2float(__float2half_rn(v.y))),
                                 pack2(__half2float(__float2half_rn(v.z)),
                                       __half2float(__float2half_rn(v.w))));
}

// in: [R][C] fp32 (batch z, stride sIn elems) -> out: [C][R] fp16 hi(/lo)
__global__ void tsplit_k(const float* __restrict__ in, long sIn,
                         __half* __restrict__ oh,
                         __half* __restrict__ ol, long sOut,
                         int R, int C) {
    __shared__ float t[32][33];
    in += (long)blockIdx.z * sIn;
    oh += (long)blockIdx.z * sOut;
    ol += (long)blockIdx.z * sOut;
    int c0 = blockIdx.x * 32, r0 = blockIdx.y * 32;
    int tx = threadIdx.x, ty = threadIdx.y;  // (32,8)
#pragma unroll
    for (int i = 0; i < 4; i++)
        t[ty + i * 8][tx] = in[(long)(r0 + ty + i * 8) * C + c0 + tx];
    __syncthreads();
#pragma unroll
    for (int i = 0; i < 4; i++) {
        float v = t[tx][ty + i * 8];
        float h, l;
        split1(v, h, l);
        long o = (long)(c0 + ty + i * 8) * R + r0 + tx;
        oh[o] = __float2half_rn(h);
        ol[o] = __float2half_rn(l);
    }
}

// z=0: Wq -> wqt_h (hi only) ; z=1: Wk -> wkt h+l ; z=2: Wv -> wvt h+l
__global__ void tsplitW_k(const float* __restrict__ Wq, const float* __restrict__ Wk,
                          const float* __restrict__ Wv,
                          __half* __restrict__ wqt_h,
                          __half* __restrict__ wkt_h, __half* __restrict__ wkt_l,
                          __half* __restrict__ wvt_h, __half* __restrict__ wvt_l) {
    const float* in; __half* oh; __half* ol;
    if (blockIdx.z == 0)      { in = Wq; oh = wqt_h; ol = nullptr; }
    else if (blockIdx.z == 1) { in = Wk; oh = wkt_h; ol = wkt_l; }
    else                      { in = Wv; oh = wvt_h; ol = wvt_l; }
    __shared__ float t[32][33];
    int c0 = blockIdx.x * 32, r0 = blockIdx.y * 32;
    int tx = threadIdx.x, ty = threadIdx.y;
#pragma unroll
    for (int i = 0; i < 4; i++)
        t[ty + i * 8][tx] = in[(long)(r0 + ty + i * 8) * Ed + c0 + tx];
    __syncthreads();
#pragma unroll
    for (int i = 0; i < 4; i++) {
        float v = t[tx][ty + i * 8];
        float h, l;
        split1(v, h, l);
        long o = (long)(c0 + ty + i * 8) * Ed + r0 + tx;
        oh[o] = __float2half_rn(h);
        if (ol) ol[o] = __float2half_rn(l);
    }
}

// mirror upper-triangle tiles of symmetric fp16 matrix into lower triangle
__global__ void mirror_k(__half* __restrict__ Gh,
                         __half* __restrict__ Gl, long sEE) {
    int bi = blockIdx.y, bj = blockIdx.x;
    if (bi > bj) return;
    __half* G = ((blockIdx.z & 1) ? Gl : Gh) + (long)(blockIdx.z >> 1) * sEE;
    __shared__ uint16_t t[32][33];
    int tx = threadIdx.x, ty = threadIdx.y;
    int r0 = bi * 32, c0 = bj * 32;
#pragma unroll
    for (int i = 0; i < 4; i++) {
        int r = ty + i * 8;
        uint16_t v;
        memcpy(&v, &G[(long)(r0 + r) * Ed + c0 + tx], 2);
        t[r][tx] = v;
    }
    __syncthreads();
#pragma unroll
    for (int i = 0; i < 4; i++) {
        int rr = ty + i * 8;
        int cc = tx;
        int dr = c0 + rr, dc = r0 + cc;
        if (dr > dc) {
            uint16_t v = t[cc][rr];
            memcpy(&G[(long)dr * Ed + dc], &v, 2);
        }
    }
}

// ===========================================================================
// vector kernels (fp32, merged by role)
// ===========================================================================
// s_b = colsum(x_b)
__global__ void coldot_k(const float* __restrict__ A, long sA,
                         float* __restrict__ y, int rows, int ldr) {
    A += (long)blockIdx.y * sA;
    y += blockIdx.y * ldr;
    int j = blockIdx.x * blockDim.x + threadIdx.x;
    float acc = 0.f;
#pragma unroll 8
    for (int i = 0; i < rows; i++) acc += A[(long)i * ldr + j];
    y[j] = acc;
}

// z=0: p_b = Wk s_b ; z=1: r_b = Wv s_b
__global__ void rowdot_pr_k(const float* __restrict__ Wk, const float* __restrict__ Wv,
                            const float* __restrict__ s,
                            float* __restrict__ p, float* __restrict__ r) {
    const float* A = blockIdx.z ? Wv : Wk;
    float* y = (blockIdx.z ? r : p) + blockIdx.y * Ed;
    const float* xv = s + blockIdx.y * Ed;
    int warp = blockIdx.x * 8 + (threadIdx.x >> 5);
    int lane = threadIdx.x & 31;
    const float* row = A + (long)warp * Ed;
    float acc = 0.f;
    for (int j = lane; j < Ed; j += 32) acc += row[j] * xv[j];
#pragma unroll
    for (int o = 16; o > 0; o >>= 1) acc += __shfl_xor_sync(0xffffffffu, acc, o);
    if (lane == 0) y[warp] = acc;
}

// independent: z=0: u2=Wq^T bk ; z=1: t1=Wk^T bq ; z=2: w1=Wo bv
__global__ void pre_k(const float* __restrict__ Wq, const float* __restrict__ bk,
                      const float* __restrict__ Wk, const float* __restrict__ bq,
                      const float* __restrict__ Wo, const float* __restrict__ bv,
                      float* __restrict__ u2, float* __restrict__ t1,
                      float* __restrict__ w1) {
    int z = blockIdx.z;
    if (z < 2) {  // coldot
        if (blockIdx.x >= Ed / 256) return;
        const float* A = z ? Wk : Wq;
        const float* w = z ? bq : bk;
        float* y = z ? t1 : u2;
        int j = blockIdx.x * 256 + threadIdx.x;
        float acc = 0.f;
#pragma unroll 8
        for (int i = 0; i < Ed; i++) acc += A[(long)i * Ed + j] * w[i];
        y[j] = acc;
    } else {      // rowdot
        int warp = blockIdx.x * 8 + (threadIdx.x >> 5);
        int lane = threadIdx.x & 31;
        const float* row = Wo + (long)warp * Ed;
        float acc = 0.f;
        for (int j = lane; j < Ed; j += 32) acc += row[j] * bv[j];
#pragma unroll
        for (int o = 16; o > 0; o >>= 1) acc += __shfl_xor_sync(0xffffffffu, acc, o);
        if (lane == 0) w1[warp] = acc;
    }
}

// dependent on p,r: z=0: u1_b=Wq^T p_b ; z=1: w2_b=Wo r_b ; z=2: dp/db
__global__ void post_k(const float* __restrict__ Wq, const float* __restrict__ p,
                       const float* __restrict__ Wo, const float* __restrict__ r,
                       const float* __restrict__ bk, const float* __restrict__ bq,
                       float* __restrict__ u1, float* __restrict__ w2,
                       float* __restrict__ dp, float* __restrict__ db) {
    int z = blockIdx.z, b = blockIdx.y;
    if (z == 0) {       // coldot batched
        if (blockIdx.x >= Ed / 256) return;
        int j = blockIdx.x * 256 + threadIdx.x;
        const float* w = p + (long)b * Ed;
        float acc = 0.f;
#pragma unroll 8
        for (int i = 0; i < Ed; i++) acc += Wq[(long)i * Ed + j] * w[i];
        u1[(long)b * Ed + j] = acc;
    } else if (z == 1) { // rowdot batched
        int warp = blockIdx.x * 8 + (threadIdx.x >> 5);
        int lane = threadIdx.x & 31;
        const float* xv = r + (long)b * Ed;
        const float* row = Wo + (long)warp * Ed;
        float acc = 0.f;
        for (int j = lane; j < Ed; j += 32) acc += row[j] * xv[j];
#pragma unroll
        for (int o = 16; o > 0; o >>= 1) acc += __shfl_xor_sync(0xffffffffu, acc, o);
        if (lane == 0) w2[(long)b * Ed + warp] = acc;
    } else {             // dots
        if (b != 0) return;
        int bid = blockIdx.x;
        if (bid > Bd) return;
        const float* a = (bid < Bd) ? p + (long)bid * Ed : bk;
        __shared__ float red[8];
        int tid = threadIdx.x;
        float acc = 0.f;
        for (int j = tid; j < Ed; j += 256) acc += a[j] * bq[j];
#pragma unroll
        for (int o = 16; o > 0; o >>= 1) acc += __shfl_xor_sync(0xffffffffu, acc, o);
        if ((tid & 31) == 0) red[tid >> 5] = acc;
        __syncthreads();
        if (tid < 8) {
            float v = red[tid];
#pragma unroll
            for (int o = 4; o > 0; o >>= 1) v += __shfl_xor_sync(0xffu, v, o);
            if (tid == 0) { if (bid < Bd) dp[bid] = v; else db[0] = v; }
        }
    }
}

// t2_b[i] = dot((Gh+Gl)[i,:], t1)
__global__ void rowdot_hf2_k(const __half* __restrict__ Ah,
                             const __half* __restrict__ Al, long sA,
                             const float* __restrict__ xv,
                             float* __restrict__ y, int cols) {
    Ah += (long)blockIdx.y * sA;
    Al += (long)blockIdx.y * sA;
    y  += blockIdx.y * cols;
    int warp = blockIdx.x * 8 + (threadIdx.x >> 5);
    int lane = threadIdx.x & 31;
    const __half* rh = Ah + (long)warp * cols;
    const __half* rl = Al + (long)warp * cols;
    float acc = 0.f;
    for (int j = lane; j < cols; j += 32)
        acc += (__half2float(rh[j]) + __half2float(rl[j])) * xv[j];
#pragma unroll
    for (int o = 16; o > 0; o >>= 1) acc += __shfl_xor_sync(0xffffffffu, acc, o);
    if (lane == 0) y[warp] = acc;
}

// d_b[i] = (Wv t2_b)[i] + bv[i]*(dp[b] + S*db) + r_b[i]*db   (fused vfin)
__global__ void dfin_k(const float* __restrict__ Wv, const float* __restrict__ t2,
                       const float* __restrict__ bv, const float* __restrict__ r,
                       const float* __restrict__ dp, const float* __restrict__ db,
                       float* __restrict__ d) {
    int b = blockIdx.y;
    int warp = blockIdx.x * 8 + (threadIdx.x >> 5);
    int lane = threadIdx.x & 31;
    const float* xv = t2 + (long)b * Ed;
    const float* row = Wv + (long)warp * Ed;
    float acc = 0.f;
    for (int j = lane; j < Ed; j += 32) acc += row[j] * xv[j];
#pragma unroll
    for (int o = 16; o > 0; o >>= 1) acc += __shfl_xor_sync(0xffffffffu, acc, o);
    if (lane == 0) {
        float dbv = db[0];
        d[(long)b * Ed + warp] = acc + bv[warp] * (dp[b] + (float)Sd * dbv)
                               + r[(long)b * Ed + warp] * dbv;
    }
}

// cb_b = SCALE * Wo d_b + bo
__global__ void rowdot_k(const float* __restrict__ A,
                         const float* __restrict__ xv, int sxv,
                         const float* __restrict__ bias,
                         float* __restrict__ y, int sy, int cols, float alpha) {
    xv += blockIdx.y * sxv;
    y  += blockIdx.y * sy;
    int warp = blockIdx.x * 8 + (threadIdx.x >> 5);
    int lane = threadIdx.x & 31;
    const float* row = A + (long)warp * cols;
    float acc = 0.f;
    for (int j = lane; j < cols; j += 32) acc += row[j] * xv[j];
#pragma unroll
    for (int o = 16; o > 0; o >>= 1) acc += __shfl_xor_sync(0xffffffffu, acc, o);
    if (lane == 0) y[warp] = alpha * acc + (bias ? bias[warp] : 0.f);
}

// ===========================================================================
// fp16 2-product split GEMM engine (R7 core; Cl now nullable)
// ===========================================================================
constexpr int OFF_A  = 0;
constexpr int OFF_BH = 16384;
constexpr int OFF_BL = 32768;
constexpr int STAGE  = 49152;
constexpr int DYN_SMEM = 4 * STAGE;  // 192 KB

__device__ __forceinline__ void issue_tile(uint32_t sdst, const __half* g,
                                           long ldK, int tid) {
#pragma unroll
    for (int i = 0; i < 2; i++) {
        int gi = tid + i * 512;
        int row = gi >> 3, c16 = gi & 7;
        uint32_t off = SWZ128((uint32_t)(row * 128 + c16 * 16));
        cp16(sdst + off, (const char*)(g + (long)row * ldK) + c16 * 16);
    }
}

__device__ __forceinline__ void compute_ks(uint32_t sb, int ks, int mw, int nw,
                                           int lane, float (&acc)[2][4][4]) {
    const uint32_t rowsel = lane & 15;
    const uint32_t ksel = (lane >> 4) * 16;
    uint32_t ah[2][4];
#pragma unroll
    for (int mt = 0; mt < 2; mt++) {
        uint32_t off = SWZ128((uint32_t)((mw + mt * 16 + rowsel) * 128 + ks * 32 + ksel));
        LDMX4(ah[mt][0], ah[mt][1], ah[mt][2], ah[mt][3], sb + OFF_A + off);
    }
    uint32_t bh[4][2], bl[4][2];
#pragma unroll
    for (int nt = 0; nt < 2; nt++) {
        uint32_t off = SWZ128((uint32_t)((nw + nt * 16 + rowsel) * 128 + ks * 32 + ksel));
        uint32_t r0, r1, r2, r3;
        LDMX4(r0, r1, r2, r3, sb + OFF_BH + off);
        bh[2 * nt][0] = r0; bh[2 * nt][1] = r2;
        bh[2 * nt + 1][0] = r1; bh[2 * nt + 1][1] = r3;
        LDMX4(r0, r1, r2, r3, sb + OFF_BL + off);
        bl[2 * nt][0] = r0; bl[2 * nt][1] = r2;
        bl[2 * nt + 1][0] = r1; bl[2 * nt + 1][1] = r3;
    }
#pragma unroll
    for (int mt = 0; mt < 2; mt++)
#pragma unroll
        for (int nf = 0; nf < 4; nf++) {
            mma16816(acc[mt][nf], ah[mt], bh[nf]);  // hi*hi
            mma16816(acc[mt][nf], ah[mt], bl[nf]);  // hi*lo
        }
}

__global__ void __launch_bounds__(512, 1) hf_gemm(
    const __half* __restrict__ Ah, long sA,
    const __half* __restrict__ Bh, const __half* __restrict__ Bl, long sB,
    float* __restrict__ Cf, long sCf,
    __half* __restrict__ Ch, __half* __restrict__ Cl, long sCb,
    int Nd, int Kd, float alpha, int mode, int tri, int dual,
    const __half* __restrict__ A2h, const __half* __restrict__ B2h,
    const __half* __restrict__ B2l, __half* __restrict__ C2h, __half* __restrict__ C2l,
    const float* __restrict__ v1, int sv1, const float* __restrict__ v2,
    const float* __restrict__ v3, const float* __restrict__ v4, int sv4, float rk)
{
    extern __shared__ char smem[];
    const int bz = blockIdx.z;
    if (dual && bz == 1) {
        Ah = A2h; Bh = B2h; Bl = B2l; Ch = C2h; Cl = C2l;
    } else {
        Ah += (long)bz * sA;
        Bh += (long)bz * sB; Bl += (long)bz * sB;
        if (Cf) Cf += (long)bz * sCf;
        if (Ch) { Ch += (long)bz * sCb; if (Cl) Cl += (long)bz * sCb; }
        if (v1) v1 += (long)bz * sv1;
        if (v4) v4 += (long)bz * sv4;
    }

    int m0, n0;
    if (tri) {
        int t = blockIdx.x, ti = 0;
        while (t >= 8 - ti) { t -= 8 - ti; ti++; }
        m0 = ti * 128;
        n0 = (ti + t) * 128;
    } else {
        m0 = blockIdx.y * 128;
        n0 = blockIdx.x * 128;
    }
    const int tid = threadIdx.x;
    const int lane = tid & 31;
    const int wid = tid >> 5;
    const int mw = (wid >> 2) * 32;
    const int nw = (wid & 3) * 32;
    const uint32_t sbase = smem_u32(smem);

    float acc[2][4][4];
#pragma unroll
    for (int mt = 0; mt < 2; mt++)
#pragma unroll
        for (int nf = 0; nf < 4; nf++)
#pragma unroll
            for (int q = 0; q < 4; q++) acc[mt][nf][q] = 0.f;

    const int nCh = Kd / 64;
    auto issue = [&](int c) {
        uint32_t sb = sbase + (uint32_t)(c & 3) * STAGE;
        long k0 = (long)c * 64;
        issue_tile(sb + OFF_A,  Ah + (long)m0 * Kd + k0, Kd, tid);
        issue_tile(sb + OFF_BH, Bh + (long)n0 * Kd + k0, Kd, tid);
        issue_tile(sb + OFF_BL, Bl + (long)n0 * Kd + k0, Kd, tid);
        asm volatile("cp.async.commit_group;" ::: "memory");
    };

    issue(0); issue(1); issue(2);
    for (int c = 0; c < nCh; c++) {
        if (c + 3 <= nCh) {
            asm volatile("cp.async.wait_group 2;" ::: "memory");
        } else if (c + 2 == nCh) {
            asm volatile("cp.async.wait_group 1;" ::: "memory");
        } else {
            asm volatile("cp.async.wait_group 0;" ::: "memory");
        }
        __syncthreads();
        if (c + 3 < nCh) issue(c + 3);
        const uint32_t sb = sbase + (uint32_t)(c & 3) * STAGE;
        compute_ks(sb, 0, mw, nw, lane, acc);
        compute_ks(sb, 1, mw, nw, lane, acc);
        compute_ks(sb, 2, mw, nw, lane, acc);
        compute_ks(sb, 3, mw, nw, lane, acc);
    }
    __syncthreads();

    // epilogue
    const int r = lane >> 2;
    const int cp = (lane & 3) * 2;
#pragma unroll
    for (int mt = 0; mt < 2; mt++)
#pragma unroll
        for (int rr = 0; rr < 2; rr++) {
            const int m = m0 + mw + mt * 16 + r + rr * 8;
            float pv = 0.f, bkv = 0.f;
            if (mode == 1) { pv = v1[m]; bkv = v3[m]; }
#pragma unroll
            for (int nf = 0; nf < 4; nf++) {
                const int nloc = nf * 8 + cp;
                const int n = n0 + nw + nloc;
                float f0 = alpha * acc[mt][nf][rr * 2 + 0];
                float f1 = alpha * acc[mt][nf][rr * 2 + 1];
                if (mode == 1) {
                    f0 += pv * v2[n + 0] + bkv * (v4[n + 0] + rk * v2[n + 0]);
                    f1 += pv * v2[n + 1] + bkv * (v4[n + 1] + rk * v2[n + 1]);
                } else if (mode == 2) {
                    f0 += v1[n + 0];
                    f1 += v1[n + 1];
                }
                long co = (long)m * Nd + n;
                if (Cf) *(float2*)(Cf + co) = make_float2(f0, f1);
                if (Ch) {
                    float h0, l0, h1, l1;
                    split1(f0, h0, l0);
                    split1(f1, h1, l1);
                    *(uint32_t*)(Ch + co) = pack2(h0, h1);
                    if (Cl) *(uint32_t*)(Cl + co) = pack2(l0, l1);
                }
            }
        }
}

// ===========================================================================
// Launch — single stream (R8 fork reverted), merged preprocessing/vectors,
// dead limbs skipped.
// ===========================================================================
extern "C" void kernel_launch(void* const* d_in, const int* in_sizes, int n_in,
                              void* d_out, int out_size)
{
    const float* x  = (const float*)d_in[0];
    const float* Wq = (const float*)d_in[1];
    const float* bq = (const float*)d_in[2];
    const float* Wk = (const float*)d_in[3];
    const float* bk = (const float*)d_in[4];
    const float* Wv = (const float*)d_in[5];
    const float* bv = (const float*)d_in[6];
    const float* Wo = (const float*)d_in[7];
    const float* bo = (const float*)d_in[8];
    float* out = (float*)d_out;

    char* scr = nullptr;
    cudaGetSymbolAddress((void**)&scr, g_scratch);
    auto HF = [&](long off) { return (__half*)(scr + off); };

    __half *xs_h = HF(OFF_XS_H);
    __half *xt_h = HF(OFF_XT_H), *xt_l = HF(OFF_XT_L);
    __half *wqt_h = HF(OFF_WQT_H);
    __half *wkt_h = HF(OFF_WKT_H), *wkt_l = HF(OFF_WKT_L);
    __half *wvt_h = HF(OFF_WVT_H), *wvt_l = HF(OFF_WVT_L);
    __half *wo_h  = HF(OFF_WO_H);
    __half *P_h = HF(OFF_P_H), *P_l = HF(OFF_P_L);
    __half *Q_h = HF(OFF_Q_H);
    __half *G_h = HF(OFF_G_H), *G_l = HF(OFF_G_L);
    __half *R_h = HF(OFF_R_H);
    __half *UT_h = HF(OFF_UT_H), *UT_l = HF(OFF_UT_L);

    float* vec = (float*)(scr + OFF_VEC);
    float* s    = vec;                 // [B][E]
    float* p    = s    + Bd * Ed;
    float* r    = p    + Bd * Ed;
    float* u1   = r    + Bd * Ed;
    float* w2   = u1   + Bd * Ed;
    float* t2   = w2   + Bd * Ed;
    float* d    = t2   + Bd * Ed;
    float* cb   = d    + Bd * Ed;
    float* u2   = cb   + Bd * Ed;      // [E]
    float* w1   = u2   + Ed;
    float* t1   = w1   + Ed;
    float* dp   = t1   + Ed;           // [B]
    float* db   = dp   + Bd;           // [1]

    const long sX = (long)Sd * Ed;     // 2M elems
    const long sXT = (long)Ed * Sd;
    const long sEE = (long)Ed * Ed;

    cudaFuncSetAttribute(hf_gemm, cudaFuncAttributeMaxDynamicSharedMemorySize, DYN_SMEM);
    dim3 blk(512);

    // ---- preprocessing (3 launches) ----
    split_hi2_k<<<dim3(Bd * sX / 4 / 256, 2), 256>>>(x, xs_h, Bd * sX / 4, Wo, wo_h, sEE / 4);
    tsplitW_k<<<dim3(32, 32, 3), dim3(32, 8)>>>(Wq, Wk, Wv, wqt_h, wkt_h, wkt_l, wvt_h, wvt_l);
    tsplit_k<<<dim3(Ed / 32, Sd / 32, Bd), dim3(32, 8)>>>(x, sX, xt_h, xt_l, sXT, Sd, Ed);

    // ---- vectors (4 launches) ----
    pre_k<<<dim3(128, 1, 3), 256>>>(Wq, bk, Wk, bq, Wo, bv, u2, t1, w1);
    coldot_k<<<dim3(Ed / 256, Bd), 256>>>(x, sX, s, Sd, Ed);
    rowdot_pr_k<<<dim3(Ed / 8, Bd, 2), 256>>>(Wk, Wv, s, p, r);
    post_k<<<dim3(128, Bd, 3), 256>>>(Wq, p, Wo, r, bk, bq, u1, w2, dp, db);

    // ---- GEMMs + cb chain ----
    // merged: z=0 -> P = Wq^T Wk (h+l) ; z=1 -> Q = Wo Wv (hi only)
    hf_gemm<<<dim3(8, 8, 2), blk, DYN_SMEM>>>(wqt_h, 0, wkt_h, wkt_l, 0,
        nullptr, 0, P_h, P_l, 0, Ed, Ed, 1.f, 0, 0, 1,
        wo_h, wvt_h, wvt_l, Q_h, nullptr,
        nullptr, 0, nullptr, nullptr, nullptr, 0, 0.f);
    // G_b = x^T x : upper-triangle tiles (36) per batch, K=S
    hf_gemm<<<dim3(36, 1, Bd), blk, DYN_SMEM>>>(xt_h, sXT, xt_h, xt_l, sXT,
        nullptr, 0, G_h, G_l, sEE, Ed, Sd, 1.f, 0, 1, 0,
        nullptr, nullptr, nullptr, nullptr, nullptr,
        nullptr, 0, nullptr, nullptr, nullptr, 0, 0.f);
    mirror_k<<<dim3(Ed / 32, Ed / 32, Bd * 2), dim3(32, 8)>>>(G_h, G_l, sEE);

    // cb chain (3 launches)
    rowdot_hf2_k<<<dim3(Ed / 8, Bd), 256>>>(G_h, G_l, sEE, t1, t2, Ed);
    dfin_k<<<dim3(Ed / 8, Bd), 256>>>(Wv, t2, bv, r, dp, db, d);
    rowdot_k<<<dim3(Ed / 8, Bd), 256>>>(Wo, d, Ed, bo, cb, Ed, Ed, SCALE_F);

    // R_b = Q G_b (hi only out; G symmetric -> row-major as B ok)
    hf_gemm<<<dim3(8, 8, Bd), blk, DYN_SMEM>>>(Q_h, 0, G_h, G_l, sEE,
        nullptr, 0, R_h, nullptr, sEE, Ed, Ed, 1.f, 0, 0, 0,
        nullptr, nullptr, nullptr, nullptr, nullptr,
        nullptr, 0, nullptr, nullptr, nullptr, 0, 0.f);
    // UT_b = R_b P^T + w2 u2^T + w1 (u1 + S u2)^T
    hf_gemm<<<dim3(8, 8, Bd), blk, DYN_SMEM>>>(R_h, sEE, P_h, P_l, 0,
        nullptr, 0, UT_h, UT_l, sEE, Ed, Ed, 1.f, 1, 0, 0,
        nullptr, nullptr, nullptr, nullptr, nullptr,
        w2, Ed, u2, w1, u1, Ed, (float)Sd);
    // out_b = SCALE * x UT^T + c_b
    hf_gemm<<<dim3(8, 16, Bd), blk, DYN_SMEM>>>(xs_h, sX, UT_h, UT_l, sEE,
        out, sX, nullptr, nullptr, 0, Ed, Ed, SCALE_F, 2, 0, 0,
        nullptr, nullptr, nullptr, nullptr, nullptr,
        cb, Ed, nullptr, nullptr, nullptr, 0, 0.f);
}

// round 10
// speedup vs baseline: 1.5801x; 1.4975x over previous
#include <cuda_runtime.h>
#include <cuda_fp16.h>
#include <cstdint>
#include <cstring>

// Problem dims (fixed by setup_inputs)
constexpr int Bd = 4;
constexpr int Sd = 2048;
constexpr int Ed = 1024;
constexpr float SCALE_F = 0.125f;
constexpr int KS = 8;   // split-K factor for matvec partials

// ===========================================================================
// scratch layout (bytes) — fp16 limb arrays (lo omitted where never read)
// ===========================================================================
constexpr long MB = 1024 * 1024;
constexpr long OFF_XS_H = 0;          // x split hi   [B][S][E]  16MB
constexpr long OFF_XT_H = 32 * MB;    // x^T split    [B][E][S]  16MB
constexpr long OFF_XT_L = 48 * MB;
constexpr long OFF_WQT_H = 64 * MB;   // Wq^T hi      [E][E]      2MB
constexpr long OFF_WKT_H = 68 * MB;
constexpr long OFF_WKT_L = 70 * MB;
constexpr long OFF_WVT_H = 72 * MB;
constexpr long OFF_WVT_L = 74 * MB;
constexpr long OFF_WO_H  = 76 * MB;   // Wo hi (no transpose)
constexpr long OFF_P_H   = 80 * MB;   // P = Wq^T Wk (both limbs)
constexpr long OFF_P_L   = 82 * MB;
constexpr long OFF_Q_H   = 84 * MB;   // Q = Wo Wv (hi only)
constexpr long OFF_G_H   = 88 * MB;   // G  [B][E][E]  8MB
constexpr long OFF_G_L   = 96 * MB;
constexpr long OFF_R_H   = 104 * MB;  // R = Q G (hi only)
constexpr long OFF_UT_H  = 120 * MB;  // U^T (both limbs)
constexpr long OFF_UT_L  = 128 * MB;
constexpr long OFF_VEC   = 136 * MB;  // fp32 vectors + matvec partials
constexpr long SCRATCH_BYTES = 138 * MB;

__device__ __align__(1024) char g_scratch[SCRATCH_BYTES];

// ===========================================================================
// helpers
// ===========================================================================
__device__ __forceinline__ uint32_t smem_u32(const void* p) {
    uint32_t a;
    asm("{ .reg .u64 t; cvta.to.shared.u64 t, %1; cvt.u32.u64 %0, t; }" : "=r"(a) : "l"(p));
    return a;
}
#define SWZ128(o) ((o) ^ (((o) >> 3) & 0x70))

__device__ __forceinline__ void split1(float v, float& h, float& l) {
    h = __half2float(__float2half_rn(v));
    l = v - h;
}
__device__ __forceinline__ uint32_t pack2(float a, float b) {
    __half ha = __float2half_rn(a), hb = __float2half_rn(b);
    uint16_t ua, ub;
    memcpy(&ua, &ha, 2); memcpy(&ub, &hb, 2);
    return (uint32_t)ua | ((uint32_t)ub << 16);
}

#define LDMX4(r0, r1, r2, r3, addr)                                            \
    asm volatile("ldmatrix.sync.aligned.m8n8.x4.shared.b16 {%0,%1,%2,%3}, [%4];" \
                 : "=r"(r0), "=r"(r1), "=r"(r2), "=r"(r3) : "r"(addr))

__device__ __forceinline__ void mma16816(float* c, const uint32_t* a, const uint32_t* b) {
    asm volatile(
        "mma.sync.aligned.m16n8k16.row.col.f32.f16.f16.f32 "
        "{%0,%1,%2,%3},{%4,%5,%6,%7},{%8,%9},{%0,%1,%2,%3};"
        : "+f"(c[0]), "+f"(c[1]), "+f"(c[2]), "+f"(c[3])
        : "r"(a[0]), "r"(a[1]), "r"(a[2]), "r"(a[3]), "r"(b[0]), "r"(b[1]));
}
__device__ __forceinline__ void cp16(uint32_t dst, const void* src) {
    asm volatile("cp.async.cg.shared.global [%0], [%1], 16;" :: "r"(dst), "l"(src));
}

// ===========================================================================
// preprocessing
// ===========================================================================
// y=0: x -> xs_h (hi only) ; y=1: Wo -> wo_h (hi only)
__global__ void split_hi2_k(const float* __restrict__ x, __half* __restrict__ xs_h, long n4x,
                            const float* __restrict__ Wo, __half* __restrict__ wo_h, long n4w) {
    long i = (long)blockIdx.x * blockDim.x + threadIdx.x;
    const float* in; __half* oh; long n4;
    if (blockIdx.y == 0) { in = x; oh = xs_h; n4 = n4x; }
    else                 { in = Wo; oh = wo_h; n4 = n4w; }
    if (i >= n4) return;
    float4 v = ((const float4*)in)[i];
    ((uint2*)oh)[i] = make_uint2(pack2(__half2float(__float2half_rn(v.x)),
                                       __half2float(__float2half_rn(v.y))),
                                 pack2(__half2float(__float2half_rn(v.z)),
                                       __half2float(__float2half_rn(v.w))));
}

// in: [R][C] fp32 (batch z, stride sIn elems) -> out: [C][R] fp16 hi/lo
__global__ void tsplit_k(const float* __restrict__ in, long sIn,
                         __half* __restrict__ oh,
                         __half* __restrict__ ol, long sOut,
                         int R, int C) {
    __shared__ float t[32][33];
    in += (long)blockIdx.z * sIn;
    oh += (long)blockIdx.z * sOut;
    ol += (long)blockIdx.z * sOut;
    int c0 = blockIdx.x * 32, r0 = blockIdx.y * 32;
    int tx = threadIdx.x, ty = threadIdx.y;  // (32,8)
#pragma unroll
    for (int i = 0; i < 4; i++)
        t[ty + i * 8][tx] = in[(long)(r0 + ty + i * 8) * C + c0 + tx];
    __syncthreads();
#pragma unroll
    for (int i = 0; i < 4; i++) {
        float v = t[tx][ty + i * 8];
        float h, l;
        split1(v, h, l);
        long o = (long)(c0 + ty + i * 8) * R + r0 + tx;
        oh[o] = __float2half_rn(h);
        ol[o] = __float2half_rn(l);
    }
}

// z=0: Wq -> wqt_h (hi only) ; z=1: Wk -> wkt h+l ; z=2: Wv -> wvt h+l
__global__ void tsplitW_k(const float* __restrict__ Wq, const float* __restrict__ Wk,
                          const float* __restrict__ Wv,
                          __half* __restrict__ wqt_h,
                          __half* __restrict__ wkt_h, __half* __restrict__ wkt_l,
                          __half* __restrict__ wvt_h, __half* __restrict__ wvt_l) {
    const float* in; __half* oh; __half* ol;
    if (blockIdx.z == 0)      { in = Wq; oh = wqt_h; ol = nullptr; }
    else if (blockIdx.z == 1) { in = Wk; oh = wkt_h; ol = wkt_l; }
    else                      { in = Wv; oh = wvt_h; ol = wvt_l; }
    __shared__ float t[32][33];
    int c0 = blockIdx.x * 32, r0 = blockIdx.y * 32;
    int tx = threadIdx.x, ty = threadIdx.y;
#pragma unroll
    for (int i = 0; i < 4; i++)
        t[ty + i * 8][tx] = in[(long)(r0 + ty + i * 8) * Ed + c0 + tx];
    __syncthreads();
#pragma unroll
    for (int i = 0; i < 4; i++) {
        float v = t[tx][ty + i * 8];
        float h, l;
        split1(v, h, l);
        long o = (long)(c0 + ty + i * 8) * Ed + r0 + tx;
        oh[o] = __float2half_rn(h);
        if (ol) ol[o] = __float2half_rn(l);
    }
}

// mirror upper-triangle tiles of symmetric fp16 matrix into lower triangle
__global__ void mirror_k(__half* __restrict__ Gh,
                         __half* __restrict__ Gl, long sEE) {
    int bi = blockIdx.y, bj = blockIdx.x;
    if (bi > bj) return;
    __half* G = ((blockIdx.z & 1) ? Gl : Gh) + (long)(blockIdx.z >> 1) * sEE;
    __shared__ uint16_t t[32][33];
    int tx = threadIdx.x, ty = threadIdx.y;
    int r0 = bi * 32, c0 = bj * 32;
#pragma unroll
    for (int i = 0; i < 4; i++) {
        int r = ty + i * 8;
        uint16_t v;
        memcpy(&v, &G[(long)(r0 + r) * Ed + c0 + tx], 2);
        t[r][tx] = v;
    }
    __syncthreads();
#pragma unroll
    for (int i = 0; i < 4; i++) {
        int rr = ty + i * 8;
        int cc = tx;
        int dr = c0 + rr, dc = r0 + cc;
        if (dr > dc) {
            uint16_t v = t[cc][rr];
            memcpy(&G[(long)dr * Ed + dc], &v, 2);
        }
    }
}

// ===========================================================================
// split-K matvec engine (coldot-shaped jobs, deterministic two-phase)
// ===========================================================================
// phase 1 jobs: z=0: Wq^T bk ; z=1: Wk^T bq ; z=2..5: colsum(x_b)
__global__ void mv1_part_k(const float* __restrict__ Wq, const float* __restrict__ bk,
                           const float* __restrict__ Wk, const float* __restrict__ bq,
                           const float* __restrict__ x, long sX,
                           float* __restrict__ part) {
    int z = blockIdx.z;
    const float* A; const float* w; int rows;
    if (z == 0)      { A = Wq; w = bk; rows = Ed; }
    else if (z == 1) { A = Wk; w = bq; rows = Ed; }
    else             { A = x + (long)(z - 2) * sX; w = nullptr; rows = Sd; }
    int j = blockIdx.x * 256 + threadIdx.x;
    int chunk = rows / KS;
    int r0 = blockIdx.y * chunk;
    float a0 = 0.f, a1 = 0.f;
    for (int i = 0; i < chunk; i += 2) {
        float w0 = w ? w[r0 + i] : 1.f;
        float w1v = w ? w[r0 + i + 1] : 1.f;
        a0 += A[(long)(r0 + i) * Ed + j] * w0;
        a1 += A[(long)(r0 + i + 1) * Ed + j] * w1v;
    }
    part[((long)z * KS + blockIdx.y) * Ed + j] = a0 + a1;
}

__global__ void mv1_red_k(const float* __restrict__ part,
                          float* __restrict__ u2, float* __restrict__ t1,
                          float* __restrict__ s) {
    int z = blockIdx.y;
    int j = blockIdx.x * 256 + threadIdx.x;
    float a = 0.f;
#pragma unroll
    for (int ks = 0; ks < KS; ks++) a += part[((long)z * KS + ks) * Ed + j];
    float* y = (z == 0) ? u2 : (z == 1) ? t1 : s + (long)(z - 2) * Ed;
    y[j] = a;
}

// phase 2: u1_b = Wq^T p_b (4 jobs)
__global__ void mv2_part_k(const float* __restrict__ Wq, const float* __restrict__ p,
                           float* __restrict__ part) {
    int b = blockIdx.z;
    const float* w = p + (long)b * Ed;
    int j = blockIdx.x * 256 + threadIdx.x;
    int chunk = Ed / KS;
    int r0 = blockIdx.y * chunk;
    float a0 = 0.f, a1 = 0.f;
    for (int i = 0; i < chunk; i += 2) {
        a0 += Wq[(long)(r0 + i) * Ed + j] * w[r0 + i];
        a1 += Wq[(long)(r0 + i + 1) * Ed + j] * w[r0 + i + 1];
    }
    part[((long)b * KS + blockIdx.y) * Ed + j] = a0 + a1;
}

__global__ void mv2_red_k(const float* __restrict__ part, float* __restrict__ u1) {
    int b = blockIdx.y;
    int j = blockIdx.x * 256 + threadIdx.x;
    float a = 0.f;
#pragma unroll
    for (int ks = 0; ks < KS; ks++) a += part[((long)b * KS + ks) * Ed + j];
    u1[(long)b * Ed + j] = a;
}

// ===========================================================================
// rowdot-shaped vector kernels (one warp per output row, coalesced)
// ===========================================================================
// z=0: p_b = Wk s_b ; z=1: r_b = Wv s_b ; z=2 (b==0): w1 = Wo bv
__global__ void rowdot_prw_k(const float* __restrict__ Wk, const float* __restrict__ Wv,
                             const float* __restrict__ Wo,
                             const float* __restrict__ s, const float* __restrict__ bv,
                             float* __restrict__ p, float* __restrict__ r,
                             float* __restrict__ w1) {
    int z = blockIdx.z, b = blockIdx.y;
    const float* A; const float* xv; float* y;
    if (z == 0)      { A = Wk; xv = s + (long)b * Ed; y = p + (long)b * Ed; }
    else if (z == 1) { A = Wv; xv = s + (long)b * Ed; y = r + (long)b * Ed; }
    else             { if (b) return; A = Wo; xv = bv; y = w1; }
    int warp = blockIdx.x * 8 + (threadIdx.x >> 5);
    int lane = threadIdx.x & 31;
    const float* row = A + (long)warp * Ed;
    float acc = 0.f;
    for (int j = lane; j < Ed; j += 32) acc += row[j] * xv[j];
#pragma unroll
    for (int o = 16; o > 0; o >>= 1) acc += __shfl_xor_sync(0xffffffffu, acc, o);
    if (lane == 0) y[warp] = acc;
}

// z=0: w2_b = Wo r_b ; z=1 (b==0): dp[bid]=p_bid.bq (bid<Bd), db=bk.bq (bid=Bd)
__global__ void w2dots_k(const float* __restrict__ Wo, const float* __restrict__ r,
                         const float* __restrict__ p, const float* __restrict__ bk,
                         const float* __restrict__ bq,
                         float* __restrict__ w2, float* __restrict__ dp,
                         float* __restrict__ db) {
    int z = blockIdx.z, b = blockIdx.y;
    if (z == 0) {
        int warp = blockIdx.x * 8 + (threadIdx.x >> 5);
        int lane = threadIdx.x & 31;
        const float* xv = r + (long)b * Ed;
        const float* row = Wo + (long)warp * Ed;
        float acc = 0.f;
        for (int j = lane; j < Ed; j += 32) acc += row[j] * xv[j];
#pragma unroll
        for (int o = 16; o > 0; o >>= 1) acc += __shfl_xor_sync(0xffffffffu, acc, o);
        if (lane == 0) w2[(long)b * Ed + warp] = acc;
    } else {
        if (b != 0) return;
        int bid = blockIdx.x;
        if (bid > Bd) return;
        const float* a = (bid < Bd) ? p + (long)bid * Ed : bk;
        __shared__ float red[8];
        int tid = threadIdx.x;
        float acc = 0.f;
        for (int j = tid; j < Ed; j += 256) acc += a[j] * bq[j];
#pragma unroll
        for (int o = 16; o > 0; o >>= 1) acc += __shfl_xor_sync(0xffffffffu, acc, o);
        if ((tid & 31) == 0) red[tid >> 5] = acc;
        __syncthreads();
        if (tid < 8) {
            float v = red[tid];
#pragma unroll
            for (int o = 4; o > 0; o >>= 1) v += __shfl_xor_sync(0xffu, v, o);
            if (tid == 0) { if (bid < Bd) dp[bid] = v; else db[0] = v; }
        }
    }
}

// t2_b[i] = dot((Gh+Gl)[i,:], t1)
__global__ void rowdot_hf2_k(const __half* __restrict__ Ah,
                             const __half* __restrict__ Al, long sA,
                             const float* __restrict__ xv,
                             float* __restrict__ y, int cols) {
    Ah += (long)blockIdx.y * sA;
    Al += (long)blockIdx.y * sA;
    y  += blockIdx.y * cols;
    int warp = blockIdx.x * 8 + (threadIdx.x >> 5);
    int lane = threadIdx.x & 31;
    const __half* rh = Ah + (long)warp * cols;
    const __half* rl = Al + (long)warp * cols;
    float acc = 0.f;
    for (int j = lane; j < cols; j += 32)
        acc += (__half2float(rh[j]) + __half2float(rl[j])) * xv[j];
#pragma unroll
    for (int o = 16; o > 0; o >>= 1) acc += __shfl_xor_sync(0xffffffffu, acc, o);
    if (lane == 0) y[warp] = acc;
}

// d_b[i] = (Wv t2_b)[i] + bv[i]*(dp[b] + S*db) + r_b[i]*db
__global__ void dfin_k(const float* __restrict__ Wv, const float* __restrict__ t2,
                       const float* __restrict__ bv, const float* __restrict__ r,
                       const float* __restrict__ dp, const float* __restrict__ db,
                       float* __restrict__ d) {
    int b = blockIdx.y;
    int warp = blockIdx.x * 8 + (threadIdx.x >> 5);
    int lane = threadIdx.x & 31;
    const float* xv = t2 + (long)b * Ed;
    const float* row = Wv + (long)warp * Ed;
    float acc = 0.f;
    for (int j = lane; j < Ed; j += 32) acc += row[j] * xv[j];
#pragma unroll
    for (int o = 16; o > 0; o >>= 1) acc += __shfl_xor_sync(0xffffffffu, acc, o);
    if (lane == 0) {
        float dbv = db[0];
        d[(long)b * Ed + warp] = acc + bv[warp] * (dp[b] + (float)Sd * dbv)
                               + r[(long)b * Ed + warp] * dbv;
    }
}

// cb_b = SCALE * Wo d_b + bo
__global__ void rowdot_k(const float* __restrict__ A,
                         const float* __restrict__ xv, int sxv,
                         const float* __restrict__ bias,
                         float* __restrict__ y, int sy, int cols, float alpha) {
    xv += blockIdx.y * sxv;
    y  += blockIdx.y * sy;
    int warp = blockIdx.x * 8 + (threadIdx.x >> 5);
    int lane = threadIdx.x & 31;
    const float* row = A + (long)warp * cols;
    float acc = 0.f;
    for (int j = lane; j < cols; j += 32) acc += row[j] * xv[j];
#pragma unroll
    for (int o = 16; o > 0; o >>= 1) acc += __shfl_xor_sync(0xffffffffu, acc, o);
    if (lane == 0) y[warp] = alpha * acc + (bias ? bias[warp] : 0.f);
}

// ===========================================================================
// fp16 2-product split GEMM engine (unchanged)
// ===========================================================================
constexpr int OFF_A  = 0;
constexpr int OFF_BH = 16384;
constexpr int OFF_BL = 32768;
constexpr int STAGE  = 49152;
constexpr int DYN_SMEM = 4 * STAGE;  // 192 KB

__device__ __forceinline__ void issue_tile(uint32_t sdst, const __half* g,
                                           long ldK, int tid) {
#pragma unroll
    for (int i = 0; i < 2; i++) {
        int gi = tid + i * 512;
        int row = gi >> 3, c16 = gi & 7;
        uint32_t off = SWZ128((uint32_t)(row * 128 + c16 * 16));
        cp16(sdst + off, (const char*)(g + (long)row * ldK) + c16 * 16);
    }
}

__device__ __forceinline__ void compute_ks(uint32_t sb, int ks, int mw, int nw,
                                           int lane, float (&acc)[2][4][4]) {
    const uint32_t rowsel = lane & 15;
    const uint32_t ksel = (lane >> 4) * 16;
    uint32_t ah[2][4];
#pragma unroll
    for (int mt = 0; mt < 2; mt++) {
        uint32_t off = SWZ128((uint32_t)((mw + mt * 16 + rowsel) * 128 + ks * 32 + ksel));
        LDMX4(ah[mt][0], ah[mt][1], ah[mt][2], ah[mt][3], sb + OFF_A + off);
    }
    uint32_t bh[4][2], bl[4][2];
#pragma unroll
    for (int nt = 0; nt < 2; nt++) {
        uint32_t off = SWZ128((uint32_t)((nw + nt * 16 + rowsel) * 128 + ks * 32 + ksel));
        uint32_t r0, r1, r2, r3;
        LDMX4(r0, r1, r2, r3, sb + OFF_BH + off);
        bh[2 * nt][0] = r0; bh[2 * nt][1] = r2;
        bh[2 * nt + 1][0] = r1; bh[2 * nt + 1][1] = r3;
        LDMX4(r0, r1, r2, r3, sb + OFF_BL + off);
        bl[2 * nt][0] = r0; bl[2 * nt][1] = r2;
        bl[2 * nt + 1][0] = r1; bl[2 * nt + 1][1] = r3;
    }
#pragma unroll
    for (int mt = 0; mt < 2; mt++)
#pragma unroll
        for (int nf = 0; nf < 4; nf++) {
            mma16816(acc[mt][nf], ah[mt], bh[nf]);  // hi*hi
            mma16816(acc[mt][nf], ah[mt], bl[nf]);  // hi*lo
        }
}

__global__ void __launch_bounds__(512, 1) hf_gemm(
    const __half* __restrict__ Ah, long sA,
    const __half* __restrict__ Bh, const __half* __restrict__ Bl, long sB,
    float* __restrict__ Cf, long sCf,
    __half* __restrict__ Ch, __half* __restrict__ Cl, long sCb,
    int Nd, int Kd, float alpha, int mode, int tri, int dual,
    const __half* __restrict__ A2h, const __half* __restrict__ B2h,
    const __half* __restrict__ B2l, __half* __restrict__ C2h, __half* __restrict__ C2l,
    const float* __restrict__ v1, int sv1, const float* __restrict__ v2,
    const float* __restrict__ v3, const float* __restrict__ v4, int sv4, float rk)
{
    extern __shared__ char smem[];
    const int bz = blockIdx.z;
    if (dual && bz == 1) {
        Ah = A2h; Bh = B2h; Bl = B2l; Ch = C2h; Cl = C2l;
    } else {
        Ah += (long)bz * sA;
        Bh += (long)bz * sB; Bl += (long)bz * sB;
        if (Cf) Cf += (long)bz * sCf;
        if (Ch) { Ch += (long)bz * sCb; if (Cl) Cl += (long)bz * sCb; }
        if (v1) v1 += (long)bz * sv1;
        if (v4) v4 += (long)bz * sv4;
    }

    int m0, n0;
    if (tri) {
        int t = blockIdx.x, ti = 0;
        while (t >= 8 - ti) { t -= 8 - ti; ti++; }
        m0 = ti * 128;
        n0 = (ti + t) * 128;
    } else {
        m0 = blockIdx.y * 128;
        n0 = blockIdx.x * 128;
    }
    const int tid = threadIdx.x;
    const int lane = tid & 31;
    const int wid = tid >> 5;
    const int mw = (wid >> 2) * 32;
    const int nw = (wid & 3) * 32;
    const uint32_t sbase = smem_u32(smem);

    float acc[2][4][4];
#pragma unroll
    for (int mt = 0; mt < 2; mt++)
#pragma unroll
        for (int nf = 0; nf < 4; nf++)
#pragma unroll
            for (int q = 0; q < 4; q++) acc[mt][nf][q] = 0.f;

    const int nCh = Kd / 64;
    auto issue = [&](int c) {
        uint32_t sb = sbase + (uint32_t)(c & 3) * STAGE;
        long k0 = (long)c * 64;
        issue_tile(sb + OFF_A,  Ah + (long)m0 * Kd + k0, Kd, tid);
        issue_tile(sb + OFF_BH, Bh + (long)n0 * Kd + k0, Kd, tid);
        issue_tile(sb + OFF_BL, Bl + (long)n0 * Kd + k0, Kd, tid);
        asm volatile("cp.async.commit_group;" ::: "memory");
    };

    issue(0); issue(1); issue(2);
    for (int c = 0; c < nCh; c++) {
        if (c + 3 <= nCh) {
            asm volatile("cp.async.wait_group 2;" ::: "memory");
        } else if (c + 2 == nCh) {
            asm volatile("cp.async.wait_group 1;" ::: "memory");
        } else {
            asm volatile("cp.async.wait_group 0;" ::: "memory");
        }
        __syncthreads();
        if (c + 3 < nCh) issue(c + 3);
        const uint32_t sb = sbase + (uint32_t)(c & 3) * STAGE;
        compute_ks(sb, 0, mw, nw, lane, acc);
        compute_ks(sb, 1, mw, nw, lane, acc);
        compute_ks(sb, 2, mw, nw, lane, acc);
        compute_ks(sb, 3, mw, nw, lane, acc);
    }
    __syncthreads();

    // epilogue
    const int r = lane >> 2;
    const int cp = (lane & 3) * 2;
#pragma unroll
    for (int mt = 0; mt < 2; mt++)
#pragma unroll
        for (int rr = 0; rr < 2; rr++) {
            const int m = m0 + mw + mt * 16 + r + rr * 8;
            float pv = 0.f, bkv = 0.f;
            if (mode == 1) { pv = v1[m]; bkv = v3[m]; }
#pragma unroll
            for (int nf = 0; nf < 4; nf++) {
                const int nloc = nf * 8 + cp;
                const int n = n0 + nw + nloc;
                float f0 = alpha * acc[mt][nf][rr * 2 + 0];
                float f1 = alpha * acc[mt][nf][rr * 2 + 1];
                if (mode == 1) {
                    f0 += pv * v2[n + 0] + bkv * (v4[n + 0] + rk * v2[n + 0]);
                    f1 += pv * v2[n + 1] + bkv * (v4[n + 1] + rk * v2[n + 1]);
                } else if (mode == 2) {
                    f0 += v1[n + 0];
                    f1 += v1[n + 1];
                }
                long co = (long)m * Nd + n;
                if (Cf) *(float2*)(Cf + co) = make_float2(f0, f1);
                if (Ch) {
                    float h0, l0, h1, l1;
                    split1(f0, h0, l0);
                    split1(f1, h1, l1);
                    *(uint32_t*)(Ch + co) = pack2(h0, h1);
                    if (Cl) *(uint32_t*)(Cl + co) = pack2(l0, l1);
                }
            }
        }
}

// ===========================================================================
// Launch — single stream; split-K matvec engine replaces slow coldots.
// ===========================================================================
extern "C" void kernel_launch(void* const* d_in, const int* in_sizes, int n_in,
                              void* d_out, int out_size)
{
    const float* x  = (const float*)d_in[0];
    const float* Wq = (const float*)d_in[1];
    const float* bq = (const float*)d_in[2];
    const float* Wk = (const float*)d_in[3];
    const float* bk = (const float*)d_in[4];
    const float* Wv = (const float*)d_in[5];
    const float* bv = (const float*)d_in[6];
    const float* Wo = (const float*)d_in[7];
    const float* bo = (const float*)d_in[8];
    float* out = (float*)d_out;

    char* scr = nullptr;
    cudaGetSymbolAddress((void**)&scr, g_scratch);
    auto HF = [&](long off) { return (__half*)(scr + off); };

    __half *xs_h = HF(OFF_XS_H);
    __half *xt_h = HF(OFF_XT_H), *xt_l = HF(OFF_XT_L);
    __half *wqt_h = HF(OFF_WQT_H);
    __half *wkt_h = HF(OFF_WKT_H), *wkt_l = HF(OFF_WKT_L);
    __half *wvt_h = HF(OFF_WVT_H), *wvt_l = HF(OFF_WVT_L);
    __half *wo_h  = HF(OFF_WO_H);
    __half *P_h = HF(OFF_P_H), *P_l = HF(OFF_P_L);
    __half *Q_h = HF(OFF_Q_H);
    __half *G_h = HF(OFF_G_H), *G_l = HF(OFF_G_L);
    __half *R_h = HF(OFF_R_H);
    __half *UT_h = HF(OFF_UT_H), *UT_l = HF(OFF_UT_L);

    float* vec = (float*)(scr + OFF_VEC);
    float* s    = vec;                 // [B][E]
    float* p    = s    + Bd * Ed;
    float* r    = p    + Bd * Ed;
    float* u1   = r    + Bd * Ed;
    float* w2   = u1   + Bd * Ed;
    float* t2   = w2   + Bd * Ed;
    float* d    = t2   + Bd * Ed;
    float* cb   = d    + Bd * Ed;
    float* u2   = cb   + Bd * Ed;      // [E]
    float* w1   = u2   + Ed;
    float* t1   = w1   + Ed;
    float* dp   = t1   + Ed;           // [B]
    float* db   = dp   + Bd;           // [1]
    float* part = db + 256;            // split-K partials (<=48K floats)

    const long sX = (long)Sd * Ed;     // 2M elems
    const long sXT = (long)Ed * Sd;
    const long sEE = (long)Ed * Ed;

    cudaFuncSetAttribute(hf_gemm, cudaFuncAttributeMaxDynamicSharedMemorySize, DYN_SMEM);
    dim3 blk(512);

    // ---- preprocessing (3 launches) ----
    split_hi2_k<<<dim3(Bd * sX / 4 / 256, 2), 256>>>(x, xs_h, Bd * sX / 4, Wo, wo_h, sEE / 4);
    tsplitW_k<<<dim3(32, 32, 3), dim3(32, 8)>>>(Wq, Wk, Wv, wqt_h, wkt_h, wkt_l, wvt_h, wvt_l);
    tsplit_k<<<dim3(Ed / 32, Sd / 32, Bd), dim3(32, 8)>>>(x, sX, xt_h, xt_l, sXT, Sd, Ed);

    // ---- vectors (6 launches, all high-parallelism) ----
    mv1_part_k<<<dim3(Ed / 256, KS, 6), 256>>>(Wq, bk, Wk, bq, x, sX, part);
    mv1_red_k<<<dim3(Ed / 256, 6), 256>>>(part, u2, t1, s);
    rowdot_prw_k<<<dim3(Ed / 8, Bd, 3), 256>>>(Wk, Wv, Wo, s, bv, p, r, w1);
    mv2_part_k<<<dim3(Ed / 256, KS, Bd), 256>>>(Wq, p, part);
    mv2_red_k<<<dim3(Ed / 256, Bd), 256>>>(part, u1);
    w2dots_k<<<dim3(Ed / 8, Bd, 2), 256>>>(Wo, r, p, bk, bq, w2, dp, db);

    // ---- GEMMs + cb chain ----
    // merged: z=0 -> P = Wq^T Wk (h+l) ; z=1 -> Q = Wo Wv (hi only)
    hf_gemm<<<dim3(8, 8, 2), blk, DYN_SMEM>>>(wqt_h, 0, wkt_h, wkt_l, 0,
        nullptr, 0, P_h, P_l, 0, Ed, Ed, 1.f, 0, 0, 1,
        wo_h, wvt_h, wvt_l, Q_h, nullptr,
        nullptr, 0, nullptr, nullptr, nullptr, 0, 0.f);
    // G_b = x^T x : upper-triangle tiles (36) per batch, K=S
    hf_gemm<<<dim3(36, 1, Bd), blk, DYN_SMEM>>>(xt_h, sXT, xt_h, xt_l, sXT,
        nullptr, 0, G_h, G_l, sEE, Ed, Sd, 1.f, 0, 1, 0,
        nullptr, nullptr, nullptr, nullptr, nullptr,
        nullptr, 0, nullptr, nullptr, nullptr, 0, 0.f);
    mirror_k<<<dim3(Ed / 32, Ed / 32, Bd * 2), dim3(32, 8)>>>(G_h, G_l, sEE);

    // cb chain (3 launches)
    rowdot_hf2_k<<<dim3(Ed / 8, Bd), 256>>>(G_h, G_l, sEE, t1, t2, Ed);
    dfin_k<<<dim3(Ed / 8, Bd), 256>>>(Wv, t2, bv, r, dp, db, d);
    rowdot_k<<<dim3(Ed / 8, Bd), 256>>>(Wo, d, Ed, bo, cb, Ed, Ed, SCALE_F);

    // R_b = Q G_b (hi only out; G symmetric -> row-major as B ok)
    hf_gemm<<<dim3(8, 8, Bd), blk, DYN_SMEM>>>(Q_h, 0, G_h, G_l, sEE,
        nullptr, 0, R_h, nullptr, sEE, Ed, Ed, 1.f, 0, 0, 0,
        nullptr, nullptr, nullptr, nullptr, nullptr,
        nullptr, 0, nullptr, nullptr, nullptr, 0, 0.f);
    // UT_b = R_b P^T + w2 u2^T + w1 (u1 + S u2)^T
    hf_gemm<<<dim3(8, 8, Bd), blk, DYN_SMEM>>>(R_h, sEE, P_h, P_l, 0,
        nullptr, 0, UT_h, UT_l, sEE, Ed, Ed, 1.f, 1, 0, 0,
        nullptr, nullptr, nullptr, nullptr, nullptr,
        w2, Ed, u2, w1, u1, Ed, (float)Sd);
    // out_b = SCALE * x UT^T + c_b
    hf_gemm<<<dim3(8, 16, Bd), blk, DYN_SMEM>>>(xs_h, sX, UT_h, UT_l, sEE,
        out, sX, nullptr, nullptr, 0, Ed, Ed, SCALE_F, 2, 0, 0,
        nullptr, nullptr, nullptr, nullptr, nullptr,
        cb, Ed, nullptr, nullptr, nullptr, 0, 0.f);
}

// round 12
// speedup vs baseline: 1.6560x; 1.0481x over previous
#include <cuda_runtime.h>
#include <cuda_fp16.h>
#include <cstdint>
#include <cstring>

// Problem dims (fixed by setup_inputs)
constexpr int Bd = 4;
constexpr int Sd = 2048;
constexpr int Ed = 1024;
constexpr float SCALE_F = 0.125f;
constexpr int KS = 32;  // split-K factor for matvec partials

// ===========================================================================
// scratch layout (bytes) — fp16 limb arrays (lo omitted where never read)
// ===========================================================================
constexpr long MB = 1024 * 1024;
constexpr long OFF_XS_H = 0;          // x split hi   [B][S][E]  16MB
constexpr long OFF_XT_H = 32 * MB;    // x^T split    [B][E][S]  16MB
constexpr long OFF_XT_L = 48 * MB;
constexpr long OFF_WQT_H = 64 * MB;   // Wq^T hi      [E][E]      2MB
constexpr long OFF_WKT_H = 68 * MB;
constexpr long OFF_WKT_L = 70 * MB;
constexpr long OFF_WVT_H = 72 * MB;
constexpr long OFF_WVT_L = 74 * MB;
constexpr long OFF_WO_H  = 76 * MB;   // Wo hi (no transpose)
constexpr long OFF_P_H   = 80 * MB;   // P = Wq^T Wk (both limbs)
constexpr long OFF_P_L   = 82 * MB;
constexpr long OFF_Q_H   = 84 * MB;   // Q = Wo Wv (hi only)
constexpr long OFF_G_H   = 88 * MB;   // G  [B][E][E]  8MB
constexpr long OFF_G_L   = 96 * MB;
constexpr long OFF_R_H   = 104 * MB;  // R = Q G (hi only)
constexpr long OFF_UT_H  = 120 * MB;  // U^T (both limbs)
constexpr long OFF_UT_L  = 128 * MB;
constexpr long OFF_VEC   = 136 * MB;  // fp32 vectors + matvec partials
constexpr long SCRATCH_BYTES = 138 * MB;

__device__ __align__(1024) char g_scratch[SCRATCH_BYTES];

// ===========================================================================
// helpers
// ===========================================================================
__device__ __forceinline__ uint32_t smem_u32(const void* p) {
    uint32_t a;
    asm("{ .reg .u64 t; cvta.to.shared.u64 t, %1; cvt.u32.u64 %0, t; }" : "=r"(a) : "l"(p));
    return a;
}
#define SWZ128(o) ((o) ^ (((o) >> 3) & 0x70))

__device__ __forceinline__ void split1(float v, float& h, float& l) {
    h = __half2float(__float2half_rn(v));
    l = v - h;
}
__device__ __forceinline__ uint32_t pack2(float a, float b) {
    __half ha = __float2half_rn(a), hb = __float2half_rn(b);
    uint16_t ua, ub;
    memcpy(&ua, &ha, 2); memcpy(&ub, &hb, 2);
    return (uint32_t)ua | ((uint32_t)ub << 16);
}

#define LDMX4(r0, r1, r2, r3, addr)                                            \
    asm volatile("ldmatrix.sync.aligned.m8n8.x4.shared.b16 {%0,%1,%2,%3}, [%4];" \
                 : "=r"(r0), "=r"(r1), "=r"(r2), "=r"(r3) : "r"(addr))

__device__ __forceinline__ void mma16816(float* c, const uint32_t* a, const uint32_t* b) {
    asm volatile(
        "mma.sync.aligned.m16n8k16.row.col.f32.f16.f16.f32 "
        "{%0,%1,%2,%3},{%4,%5,%6,%7},{%8,%9},{%0,%1,%2,%3};"
        : "+f"(c[0]), "+f"(c[1]), "+f"(c[2]), "+f"(c[3])
        : "r"(a[0]), "r"(a[1]), "r"(a[2]), "r"(a[3]), "r"(b[0]), "r"(b[1]));
}
__device__ __forceinline__ void cp16(uint32_t dst, const void* src) {
    asm volatile("cp.async.cg.shared.global [%0], [%1], 16;" :: "r"(dst), "l"(src));
}

// ===========================================================================
// preprocessing
// ===========================================================================
// Wo -> wo_h (hi only, row-major)
__global__ void split_wo_k(const float* __restrict__ Wo, __half* __restrict__ wo_h, long n4) {
    long i = (long)blockIdx.x * blockDim.x + threadIdx.x;
    if (i >= n4) return;
    float4 v = ((const float4*)Wo)[i];
    ((uint2*)wo_h)[i] = make_uint2(pack2(__half2float(__float2half_rn(v.x)),
                                         __half2float(__float2half_rn(v.y))),
                                   pack2(__half2float(__float2half_rn(v.z)),
                                         __half2float(__float2half_rn(v.w))));
}

// fused x preprocessing: single read of x per tile
//   xs_h[r][c] = hi(x[r][c])  (row-major, coalesced on load path)
//   xt_h[c][r], xt_l[c][r]    (transposed hi/lo)
__global__ void xsplit_k(const float* __restrict__ x, long sIn,
                         __half* __restrict__ xs_h, long sXs,
                         __half* __restrict__ xt_h, __half* __restrict__ xt_l, long sXt) {
    __shared__ float t[32][33];
    x    += (long)blockIdx.z * sIn;
    xs_h += (long)blockIdx.z * sXs;
    xt_h += (long)blockIdx.z * sXt;
    xt_l += (long)blockIdx.z * sXt;
    int c0 = blockIdx.x * 32, r0 = blockIdx.y * 32;
    int tx = threadIdx.x, ty = threadIdx.y;  // (32,8)
#pragma unroll
    for (int i = 0; i < 4; i++) {
        int rr = r0 + ty + i * 8;
        float v = x[(long)rr * Ed + c0 + tx];
        t[ty + i * 8][tx] = v;
        xs_h[(long)rr * Ed + c0 + tx] = __float2half_rn(v);
    }
    __syncthreads();
#pragma unroll
    for (int i = 0; i < 4; i++) {
        float v = t[tx][ty + i * 8];
        float h, l;
        split1(v, h, l);
        long o = (long)(c0 + ty + i * 8) * Sd + r0 + tx;
        xt_h[o] = __float2half_rn(h);
        xt_l[o] = __float2half_rn(l);
    }
}

// z=0: Wq -> wqt_h (hi only) ; z=1: Wk -> wkt h+l ; z=2: Wv -> wvt h+l
__global__ void tsplitW_k(const float* __restrict__ Wq, const float* __restrict__ Wk,
                          const float* __restrict__ Wv,
                          __half* __restrict__ wqt_h,
                          __half* __restrict__ wkt_h, __half* __restrict__ wkt_l,
                          __half* __restrict__ wvt_h, __half* __restrict__ wvt_l) {
    const float* in; __half* oh; __half* ol;
    if (blockIdx.z == 0)      { in = Wq; oh = wqt_h; ol = nullptr; }
    else if (blockIdx.z == 1) { in = Wk; oh = wkt_h; ol = wkt_l; }
    else                      { in = Wv; oh = wvt_h; ol = wvt_l; }
    __shared__ float t[32][33];
    int c0 = blockIdx.x * 32, r0 = blockIdx.y * 32;
    int tx = threadIdx.x, ty = threadIdx.y;
#pragma unroll
    for (int i = 0; i < 4; i++)
        t[ty + i * 8][tx] = in[(long)(r0 + ty + i * 8) * Ed + c0 + tx];
    __syncthreads();
#pragma unroll
    for (int i = 0; i < 4; i++) {
        float v = t[tx][ty + i * 8];
        float h, l;
        split1(v, h, l);
        long o = (long)(c0 + ty + i * 8) * Ed + r0 + tx;
        oh[o] = __float2half_rn(h);
        if (ol) ol[o] = __float2half_rn(l);
    }
}

// mirror upper-triangle tiles of symmetric fp16 matrix into lower triangle
__global__ void mirror_k(__half* __restrict__ Gh,
                         __half* __restrict__ Gl, long sEE) {
    int bi = blockIdx.y, bj = blockIdx.x;
    if (bi > bj) return;
    __half* G = ((blockIdx.z & 1) ? Gl : Gh) + (long)(blockIdx.z >> 1) * sEE;
    __shared__ uint16_t t[32][33];
    int tx = threadIdx.x, ty = threadIdx.y;
    int r0 = bi * 32, c0 = bj * 32;
#pragma unroll
    for (int i = 0; i < 4; i++) {
        int r = ty + i * 8;
        uint16_t v;
        memcpy(&v, &G[(long)(r0 + r) * Ed + c0 + tx], 2);
        t[r][tx] = v;
    }
    __syncthreads();
#pragma unroll
    for (int i = 0; i < 4; i++) {
        int rr = ty + i * 8;
        int cc = tx;
        int dr = c0 + rr, dc = r0 + cc;
        if (dr > dc) {
            uint16_t v = t[cc][rr];
            memcpy(&G[(long)dr * Ed + dc], &v, 2);
        }
    }
}

// ===========================================================================
// split-K matvec engine (coldot-shaped jobs, deterministic two-phase)
// ===========================================================================
// phase 1 jobs: z=0: Wq^T bk ; z=1: Wk^T bq ; z=2..5: colsum(x_b)
__global__ void mv1_part_k(const float* __restrict__ Wq, const float* __restrict__ bk,
                           const float* __restrict__ Wk, const float* __restrict__ bq,
                           const float* __restrict__ x, long sX,
                           float* __restrict__ part) {
    int z = blockIdx.z;
    const float* A; const float* w; int rows;
    if (z == 0)      { A = Wq; w = bk; rows = Ed; }
    else if (z == 1) { A = Wk; w = bq; rows = Ed; }
    else             { A = x + (long)(z - 2) * sX; w = nullptr; rows = Sd; }
    int j = blockIdx.x * 256 + threadIdx.x;
    int chunk = rows / KS;
    int r0 = blockIdx.y * chunk;
    float a0 = 0.f, a1 = 0.f;
    for (int i = 0; i < chunk; i += 2) {
        float w0 = w ? w[r0 + i] : 1.f;
        float w1v = w ? w[r0 + i + 1] : 1.f;
        a0 += A[(long)(r0 + i) * Ed + j] * w0;
        a1 += A[(long)(r0 + i + 1) * Ed + j] * w1v;
    }
    part[((long)z * KS + blockIdx.y) * Ed + j] = a0 + a1;
}

__global__ void mv1_red_k(const float* __restrict__ part,
                          float* __restrict__ u2, float* __restrict__ t1,
                          float* __restrict__ s) {
    int z = blockIdx.y;
    int j = blockIdx.x * 256 + threadIdx.x;
    float a = 0.f;
#pragma unroll
    for (int ks = 0; ks < KS; ks++) a += part[((long)z * KS + ks) * Ed + j];
    float* y = (z == 0) ? u2 : (z == 1) ? t1 : s + (long)(z - 2) * Ed;
    y[j] = a;
}

// phase 2: u1_b = Wq^T p_b (4 jobs)
__global__ void mv2_part_k(const float* __restrict__ Wq, const float* __restrict__ p,
                           float* __restrict__ part) {
    int b = blockIdx.z;
    const float* w = p + (long)b * Ed;
    int j = blockIdx.x * 256 + threadIdx.x;
    int chunk = Ed / KS;
    int r0 = blockIdx.y * chunk;
    float a0 = 0.f, a1 = 0.f;
    for (int i = 0; i < chunk; i += 2) {
        a0 += Wq[(long)(r0 + i) * Ed + j] * w[r0 + i];
        a1 += Wq[(long)(r0 + i + 1) * Ed + j] * w[r0 + i + 1];
    }
    part[((long)b * KS + blockIdx.y) * Ed + j] = a0 + a1;
}

__global__ void mv2_red_k(const float* __restrict__ part, float* __restrict__ u1) {
    int b = blockIdx.y;
    int j = blockIdx.x * 256 + threadIdx.x;
    float a = 0.f;
#pragma unroll
    for (int ks = 0; ks < KS; ks++) a += part[((long)b * KS + ks) * Ed + j];
    u1[(long)b * Ed + j] = a;
}

// ===========================================================================
// rowdot-shaped vector kernels (one warp per output row, coalesced)
// ===========================================================================
// z=0: p_b = Wk s_b ; z=1: r_b = Wv s_b ; z=2 (b==0): w1 = Wo bv
__global__ void rowdot_prw_k(const float* __restrict__ Wk, const float* __restrict__ Wv,
                             const float* __restrict__ Wo,
                             const float* __restrict__ s, const float* __restrict__ bv,
                             float* __restrict__ p, float* __restrict__ r,
                             float* __restrict__ w1) {
    int z = blockIdx.z, b = blockIdx.y;
    const float* A; const float* xv; float* y;
    if (z == 0)      { A = Wk; xv = s + (long)b * Ed; y = p + (long)b * Ed; }
    else if (z == 1) { A = Wv; xv = s + (long)b * Ed; y = r + (long)b * Ed; }
    else             { if (b) return; A = Wo; xv = bv; y = w1; }
    int warp = blockIdx.x * 8 + (threadIdx.x >> 5);
    int lane = threadIdx.x & 31;
    const float* row = A + (long)warp * Ed;
    float acc = 0.f;
    for (int j = lane; j < Ed; j += 32) acc += row[j] * xv[j];
#pragma unroll
    for (int o = 16; o > 0; o >>= 1) acc += __shfl_xor_sync(0xffffffffu, acc, o);
    if (lane == 0) y[warp] = acc;
}

// z=0: w2_b = Wo r_b ; z=1 (b==0): dp[bid]=p_bid.bq (bid<Bd), db=bk.bq (bid=Bd)
__global__ void w2dots_k(const float* __restrict__ Wo, const float* __restrict__ r,
                         const float* __restrict__ p, const float* __restrict__ bk,
                         const float* __restrict__ bq,
                         float* __restrict__ w2, float* __restrict__ dp,
                         float* __restrict__ db) {
    int z = blockIdx.z, b = blockIdx.y;
    if (z == 0) {
        int warp = blockIdx.x * 8 + (threadIdx.x >> 5);
        int lane = threadIdx.x & 31;
        const float* xv = r + (long)b * Ed;
        const float* row = Wo + (long)warp * Ed;
        float acc = 0.f;
        for (int j = lane; j < Ed; j += 32) acc += row[j] * xv[j];
#pragma unroll
        for (int o = 16; o > 0; o >>= 1) acc += __shfl_xor_sync(0xffffffffu, acc, o);
        if (lane == 0) w2[(long)b * Ed + warp] = acc;
    } else {
        if (b != 0) return;
        int bid = blockIdx.x;
        if (bid > Bd) return;
        const float* a = (bid < Bd) ? p + (long)bid * Ed : bk;
        __shared__ float red[8];
        int tid = threadIdx.x;
        float acc = 0.f;
        for (int j = tid; j < Ed; j += 256) acc += a[j] * bq[j];
#pragma unroll
        for (int o = 16; o > 0; o >>= 1) acc += __shfl_xor_sync(0xffffffffu, acc, o);
        if ((tid & 31) == 0) red[tid >> 5] = acc;
        __syncthreads();
        if (tid < 8) {
            float v = red[tid];
#pragma unroll
            for (int o = 4; o > 0; o >>= 1) v += __shfl_xor_sync(0xffu, v, o);
            if (tid == 0) { if (bid < Bd) dp[bid] = v; else db[0] = v; }
        }
    }
}

// t2_b[i] = dot((Gh+Gl)[i,:], t1)
__global__ void rowdot_hf2_k(const __half* __restrict__ Ah,
                             const __half* __restrict__ Al, long sA,
                             const float* __restrict__ xv,
                             float* __restrict__ y, int cols) {
    Ah += (long)blockIdx.y * sA;
    Al += (long)blockIdx.y * sA;
    y  += blockIdx.y * cols;
    int warp = blockIdx.x * 8 + (threadIdx.x >> 5);
    int lane = threadIdx.x & 31;
    const __half* rh = Ah + (long)warp * cols;
    const __half* rl = Al + (long)warp * cols;
    float acc = 0.f;
    for (int j = lane; j < cols; j += 32)
        acc += (__half2float(rh[j]) + __half2float(rl[j])) * xv[j];
#pragma unroll
    for (int o = 16; o > 0; o >>= 1) acc += __shfl_xor_sync(0xffffffffu, acc, o);
    if (lane == 0) y[warp] = acc;
}

// d_b[i] = (Wv t2_b)[i] + bv[i]*(dp[b] + S*db) + r_b[i]*db
__global__ void dfin_k(const float* __restrict__ Wv, const float* __restrict__ t2,
                       const float* __restrict__ bv, const float* __restrict__ r,
                       const float* __restrict__ dp, const float* __restrict__ db,
                       float* __restrict__ d) {
    int b = blockIdx.y;
    int warp = blockIdx.x * 8 + (threadIdx.x >> 5);
    int lane = threadIdx.x & 31;
    const float* xv = t2 + (long)b * Ed;
    const float* row = Wv + (long)warp * Ed;
    float acc = 0.f;
    for (int j = lane; j < Ed; j += 32) acc += row[j] * xv[j];
#pragma unroll
    for (int o = 16; o > 0; o >>= 1) acc += __shfl_xor_sync(0xffffffffu, acc, o);
    if (lane == 0) {
        float dbv = db[0];
        d[(long)b * Ed + warp] = acc + bv[warp] * (dp[b] + (float)Sd * dbv)
                               + r[(long)b * Ed + warp] * dbv;
    }
}

// cb_b = SCALE * Wo d_b + bo
__global__ void rowdot_k(const float* __restrict__ A,
                         const float* __restrict__ xv, int sxv,
                         const float* __restrict__ bias,
                         float* __restrict__ y, int sy, int cols, float alpha) {
    xv += blockIdx.y * sxv;
    y  += blockIdx.y * sy;
    int warp = blockIdx.x * 8 + (threadIdx.x >> 5);
    int lane = threadIdx.x & 31;
    const float* row = A + (long)warp * cols;
    float acc = 0.f;
    for (int j = lane; j < cols; j += 32) acc += row[j] * xv[j];
#pragma unroll
    for (int o = 16; o > 0; o >>= 1) acc += __shfl_xor_sync(0xffffffffu, acc, o);
    if (lane == 0) y[warp] = alpha * acc + (bias ? bias[warp] : 0.f);
}

// ===========================================================================
// fp16 2-product split GEMM engine (unchanged)
// ===========================================================================
constexpr int OFF_A  = 0;
constexpr int OFF_BH = 16384;
constexpr int OFF_BL = 32768;
constexpr int STAGE  = 49152;
constexpr int DYN_SMEM = 4 * STAGE;  // 192 KB

__device__ __forceinline__ void issue_tile(uint32_t sdst, const __half* g,
                                           long ldK, int tid) {
#pragma unroll
    for (int i = 0; i < 2; i++) {
        int gi = tid + i * 512;
        int row = gi >> 3, c16 = gi & 7;
        uint32_t off = SWZ128((uint32_t)(row * 128 + c16 * 16));
        cp16(sdst + off, (const char*)(g + (long)row * ldK) + c16 * 16);
    }
}

__device__ __forceinline__ void compute_ks(uint32_t sb, int ks, int mw, int nw,
                                           int lane, float (&acc)[2][4][4]) {
    const uint32_t rowsel = lane & 15;
    const uint32_t ksel = (lane >> 4) * 16;
    uint32_t ah[2][4];
#pragma unroll
    for (int mt = 0; mt < 2; mt++) {
        uint32_t off = SWZ128((uint32_t)((mw + mt * 16 + rowsel) * 128 + ks * 32 + ksel));
        LDMX4(ah[mt][0], ah[mt][1], ah[mt][2], ah[mt][3], sb + OFF_A + off);
    }
    uint32_t bh[4][2], bl[4][2];
#pragma unroll
    for (int nt = 0; nt < 2; nt++) {
        uint32_t off = SWZ128((uint32_t)((nw + nt * 16 + rowsel) * 128 + ks * 32 + ksel));
        uint32_t r0, r1, r2, r3;
        LDMX4(r0, r1, r2, r3, sb + OFF_BH + off);
        bh[2 * nt][0] = r0; bh[2 * nt][1] = r2;
        bh[2 * nt + 1][0] = r1; bh[2 * nt + 1][1] = r3;
        LDMX4(r0, r1, r2, r3, sb + OFF_BL + off);
        bl[2 * nt][0] = r0; bl[2 * nt][1] = r2;
        bl[2 * nt + 1][0] = r1; bl[2 * nt + 1][1] = r3;
    }
#pragma unroll
    for (int mt = 0; mt < 2; mt++)
#pragma unroll
        for (int nf = 0; nf < 4; nf++) {
            mma16816(acc[mt][nf], ah[mt], bh[nf]);  // hi*hi
            mma16816(acc[mt][nf], ah[mt], bl[nf]);  // hi*lo
        }
}

__global__ void __launch_bounds__(512, 1) hf_gemm(
    const __half* __restrict__ Ah, long sA,
    const __half* __restrict__ Bh, const __half* __restrict__ Bl, long sB,
    float* __restrict__ Cf, long sCf,
    __half* __restrict__ Ch, __half* __restrict__ Cl, long sCb,
    int Nd, int Kd, float alpha, int mode, int tri, int dual,
    const __half* __restrict__ A2h, const __half* __restrict__ B2h,
    const __half* __restrict__ B2l, __half* __restrict__ C2h, __half* __restrict__ C2l,
    const float* __restrict__ v1, int sv1, const float* __restrict__ v2,
    const float* __restrict__ v3, const float* __restrict__ v4, int sv4, float rk)
{
    extern __shared__ char smem[];
    const int bz = blockIdx.z;
    if (dual && bz == 1) {
        Ah = A2h; Bh = B2h; Bl = B2l; Ch = C2h; Cl = C2l;
    } else {
        Ah += (long)bz * sA;
        Bh += (long)bz * sB; Bl += (long)bz * sB;
        if (Cf) Cf += (long)bz * sCf;
        if (Ch) { Ch += (long)bz * sCb; if (Cl) Cl += (long)bz * sCb; }
        if (v1) v1 += (long)bz * sv1;
        if (v4) v4 += (long)bz * sv4;
    }

    int m0, n0;
    if (tri) {
        int t = blockIdx.x, ti = 0;
        while (t >= 8 - ti) { t -= 8 - ti; ti++; }
        m0 = ti * 128;
        n0 = (ti + t) * 128;
    } else {
        m0 = blockIdx.y * 128;
        n0 = blockIdx.x * 128;
    }
    const int tid = threadIdx.x;
    const int lane = tid & 31;
    const int wid = tid >> 5;
    const int mw = (wid >> 2) * 32;
    const int nw = (wid & 3) * 32;
    const uint32_t sbase = smem_u32(smem);

    float acc[2][4][4];
#pragma unroll
    for (int mt = 0; mt < 2; mt++)
#pragma unroll
        for (int nf = 0; nf < 4; nf++)
#pragma unroll
            for (int q = 0; q < 4; q++) acc[mt][nf][q] = 0.f;

    const int nCh = Kd / 64;
    auto issue = [&](int c) {
        uint32_t sb = sbase + (uint32_t)(c & 3) * STAGE;
        long k0 = (long)c * 64;
        issue_tile(sb + OFF_A,  Ah + (long)m0 * Kd + k0, Kd, tid);
        issue_tile(sb + OFF_BH, Bh + (long)n0 * Kd + k0, Kd, tid);
        issue_tile(sb + OFF_BL, Bl + (long)n0 * Kd + k0, Kd, tid);
        asm volatile("cp.async.commit_group;" ::: "memory");
    };

    issue(0); issue(1); issue(2);
    for (int c = 0; c < nCh; c++) {
        if (c + 3 <= nCh) {
            asm volatile("cp.async.wait_group 2;" ::: "memory");
        } else if (c + 2 == nCh) {
            asm volatile("cp.async.wait_group 1;" ::: "memory");
        } else {
            asm volatile("cp.async.wait_group 0;" ::: "memory");
        }
        __syncthreads();
        if (c + 3 < nCh) issue(c + 3);
        const uint32_t sb = sbase + (uint32_t)(c & 3) * STAGE;
        compute_ks(sb, 0, mw, nw, lane, acc);
        compute_ks(sb, 1, mw, nw, lane, acc);
        compute_ks(sb, 2, mw, nw, lane, acc);
        compute_ks(sb, 3, mw, nw, lane, acc);
    }
    __syncthreads();

    // epilogue
    const int r = lane >> 2;
    const int cp = (lane & 3) * 2;
#pragma unroll
    for (int mt = 0; mt < 2; mt++)
#pragma unroll
        for (int rr = 0; rr < 2; rr++) {
            const int m = m0 + mw + mt * 16 + r + rr * 8;
            float pv = 0.f, bkv = 0.f;
            if (mode == 1) { pv = v1[m]; bkv = v3[m]; }
#pragma unroll
            for (int nf = 0; nf < 4; nf++) {
                const int nloc = nf * 8 + cp;
                const int n = n0 + nw + nloc;
                float f0 = alpha * acc[mt][nf][rr * 2 + 0];
                float f1 = alpha * acc[mt][nf][rr * 2 + 1];
                if (mode == 1) {
                    f0 += pv * v2[n + 0] + bkv * (v4[n + 0] + rk * v2[n + 0]);
                    f1 += pv * v2[n + 1] + bkv * (v4[n + 1] + rk * v2[n + 1]);
                } else if (mode == 2) {
                    f0 += v1[n + 0];
                    f1 += v1[n + 1];
                }
                long co = (long)m * Nd + n;
                if (Cf) *(float2*)(Cf + co) = make_float2(f0, f1);
                if (Ch) {
                    float h0, l0, h1, l1;
                    split1(f0, h0, l0);
                    split1(f1, h1, l1);
                    *(uint32_t*)(Ch + co) = pack2(h0, h1);
                    if (Cl) *(uint32_t*)(Cl + co) = pack2(l0, l1);
                }
            }
        }
}

// ===========================================================================
// Launch — single stream; fused x split, KS=32 matvecs.
// ===========================================================================
extern "C" void kernel_launch(void* const* d_in, const int* in_sizes, int n_in,
                              void* d_out, int out_size)
{
    const float* x  = (const float*)d_in[0];
    const float* Wq = (const float*)d_in[1];
    const float* bq = (const float*)d_in[2];
    const float* Wk = (const float*)d_in[3];
    const float* bk = (const float*)d_in[4];
    const float* Wv = (const float*)d_in[5];
    const float* bv = (const float*)d_in[6];
    const float* Wo = (const float*)d_in[7];
    const float* bo = (const float*)d_in[8];
    float* out = (float*)d_out;

    char* scr = nullptr;
    cudaGetSymbolAddress((void**)&scr, g_scratch);
    auto HF = [&](long off) { return (__half*)(scr + off); };

    __half *xs_h = HF(OFF_XS_H);
    __half *xt_h = HF(OFF_XT_H), *xt_l = HF(OFF_XT_L);
    __half *wqt_h = HF(OFF_WQT_H);
    __half *wkt_h = HF(OFF_WKT_H), *wkt_l = HF(OFF_WKT_L);
    __half *wvt_h = HF(OFF_WVT_H), *wvt_l = HF(OFF_WVT_L);
    __half *wo_h  = HF(OFF_WO_H);
    __half *P_h = HF(OFF_P_H), *P_l = HF(OFF_P_L);
    __half *Q_h = HF(OFF_Q_H);
    __half *G_h = HF(OFF_G_H), *G_l = HF(OFF_G_L);
    __half *R_h = HF(OFF_R_H);
    __half *UT_h = HF(OFF_UT_H), *UT_l = HF(OFF_UT_L);

    float* vec = (float*)(scr + OFF_VEC);
    float* s    = vec;                 // [B][E]
    float* p    = s    + Bd * Ed;
    float* r    = p    + Bd * Ed;
    float* u1   = r    + Bd * Ed;
    float* w2   = u1   + Bd * Ed;
    float* t2   = w2   + Bd * Ed;
    float* d    = t2   + Bd * Ed;
    float* cb   = d    + Bd * Ed;
    float* u2   = cb   + Bd * Ed;      // [E]
    float* w1   = u2   + Ed;
    float* t1   = w1   + Ed;
    float* dp   = t1   + Ed;           // [B]
    float* db   = dp   + Bd;           // [1]
    float* part = db + 256;            // split-K partials (6*KS*Ed floats ≈ 768KB)

    const long sX = (long)Sd * Ed;     // 2M elems
    const long sXT = (long)Ed * Sd;
    const long sEE = (long)Ed * Ed;

    cudaFuncSetAttribute(hf_gemm, cudaFuncAttributeMaxDynamicSharedMemorySize, DYN_SMEM);
    dim3 blk(512);

    // ---- preprocessing (3 launches; x read exactly once) ----
    xsplit_k<<<dim3(Ed / 32, Sd / 32, Bd), dim3(32, 8)>>>(x, sX, xs_h, sX, xt_h, xt_l, sXT);
    tsplitW_k<<<dim3(32, 32, 3), dim3(32, 8)>>>(Wq, Wk, Wv, wqt_h, wkt_h, wkt_l, wvt_h, wvt_l);
    split_wo_k<<<sEE / 4 / 256, 256>>>(Wo, wo_h, sEE / 4);

    // ---- vectors (6 launches, split-K KS=32) ----
    mv1_part_k<<<dim3(Ed / 256, KS, 6), 256>>>(Wq, bk, Wk, bq, x, sX, part);
    mv1_red_k<<<dim3(Ed / 256, 6), 256>>>(part, u2, t1, s);
    rowdot_prw_k<<<dim3(Ed / 8, Bd, 3), 256>>>(Wk, Wv, Wo, s, bv, p, r, w1);
    mv2_part_k<<<dim3(Ed / 256, KS, Bd), 256>>>(Wq, p, part);
    mv2_red_k<<<dim3(Ed / 256, Bd), 256>>>(part, u1);
    w2dots_k<<<dim3(Ed / 8, Bd, 2), 256>>>(Wo, r, p, bk, bq, w2, dp, db);

    // ---- GEMMs + cb chain ----
    // merged: z=0 -> P = Wq^T Wk (h+l) ; z=1 -> Q = Wo Wv (hi only)
    hf_gemm<<<dim3(8, 8, 2), blk, DYN_SMEM>>>(wqt_h, 0, wkt_h, wkt_l, 0,
        nullptr, 0, P_h, P_l, 0, Ed, Ed, 1.f, 0, 0, 1,
        wo_h, wvt_h, wvt_l, Q_h, nullptr,
        nullptr, 0, nullptr, nullptr, nullptr, 0, 0.f);
    // G_b = x^T x : upper-triangle tiles (36) per batch, K=S
    hf_gemm<<<dim3(36, 1, Bd), blk, DYN_SMEM>>>(xt_h, sXT, xt_h, xt_l, sXT,
        nullptr, 0, G_h, G_l, sEE, Ed, Sd, 1.f, 0, 1, 0,
        nullptr, nullptr, nullptr, nullptr, nullptr,
        nullptr, 0, nullptr, nullptr, nullptr, 0, 0.f);
    mirror_k<<<dim3(Ed / 32, Ed / 32, Bd * 2), dim3(32, 8)>>>(G_h, G_l, sEE);

    // cb chain (3 launches)
    rowdot_hf2_k<<<dim3(Ed / 8, Bd), 256>>>(G_h, G_l, sEE, t1, t2, Ed);
    dfin_k<<<dim3(Ed / 8, Bd), 256>>>(Wv, t2, bv, r, dp, db, d);
    rowdot_k<<<dim3(Ed / 8, Bd), 256>>>(Wo, d, Ed, bo, cb, Ed, Ed, SCALE_F);

    // R_b = Q G_b (hi only out; G symmetric -> row-major as B ok)
    hf_gemm<<<dim3(8, 8, Bd), blk, DYN_SMEM>>>(Q_h, 0, G_h, G_l, sEE,
        nullptr, 0, R_h, nullptr, sEE, Ed, Ed, 1.f, 0, 0, 0,
        nullptr, nullptr, nullptr, nullptr, nullptr,
        nullptr, 0, nullptr, nullptr, nullptr, 0, 0.f);
    // UT_b = R_b P^T + w2 u2^T + w1 (u1 + S u2)^T
    hf_gemm<<<dim3(8, 8, Bd), blk, DYN_SMEM>>>(R_h, sEE, P_h, P_l, 0,
        nullptr, 0, UT_h, UT_l, sEE, Ed, Ed, 1.f, 1, 0, 0,
        nullptr, nullptr, nullptr, nullptr, nullptr,
        w2, Ed, u2, w1, u1, Ed, (float)Sd);
    // out_b = SCALE * x UT^T + c_b
    hf_gemm<<<dim3(8, 16, Bd), blk, DYN_SMEM>>>(xs_h, sX, UT_h, UT_l, sEE,
        out, sX, nullptr, nullptr, 0, Ed, Ed, SCALE_F, 2, 0, 0,
        nullptr, nullptr, nullptr, nullptr, nullptr,
        cb, Ed, nullptr, nullptr, nullptr, 0, 0.f);
}

// round 13
// speedup vs baseline: 2.6592x; 1.6058x over previous
#include <cuda_runtime.h>
#include <cuda_fp16.h>
#include <cstdint>
#include <cstring>

// Problem dims (fixed by setup_inputs)
constexpr int Bd = 4;
constexpr int Sd = 2048;
constexpr int Ed = 1024;
constexpr float SCALE_F = 0.125f;
constexpr int KS = 32;   // split-K factor for weight matvecs
constexpr int CS = Sd / 32;  // 64 colsum tile-partials per batch

// ===========================================================================
// scratch layout (bytes) — fp16 hi-limb arrays only (1-product engine)
// ===========================================================================
constexpr long MB = 1024 * 1024;
constexpr long OFF_XS_H = 0;          // x hi   [B][S][E]  16MB
constexpr long OFF_XT_H = 32 * MB;    // x^T hi [B][E][S]  16MB
constexpr long OFF_WQT_H = 64 * MB;   // Wq^T hi [E][E]     2MB
constexpr long OFF_WKT_H = 68 * MB;
constexpr long OFF_WVT_H = 72 * MB;
constexpr long OFF_WO_H  = 76 * MB;   // Wo hi (no transpose)
constexpr long OFF_P_H   = 80 * MB;   // P = Wq^T Wk
constexpr long OFF_Q_H   = 84 * MB;   // Q = Wo Wv
constexpr long OFF_G_H   = 88 * MB;   // G  [B][E][E]  8MB
constexpr long OFF_R_H   = 104 * MB;  // R = Q G
constexpr long OFF_UT_H  = 120 * MB;  // U^T
constexpr long OFF_VEC   = 130 * MB;  // fp32 vectors + partials (~3MB used)
constexpr long SCRATCH_BYTES = 136 * MB;

__device__ __align__(1024) char g_scratch[SCRATCH_BYTES];

// ===========================================================================
// helpers
// ===========================================================================
__device__ __forceinline__ uint32_t smem_u32(const void* p) {
    uint32_t a;
    asm("{ .reg .u64 t; cvta.to.shared.u64 t, %1; cvt.u32.u64 %0, t; }" : "=r"(a) : "l"(p));
    return a;
}
#define SWZ128(o) ((o) ^ (((o) >> 3) & 0x70))

__device__ __forceinline__ uint32_t pack2(float a, float b) {
    __half ha = __float2half_rn(a), hb = __float2half_rn(b);
    uint16_t ua, ub;
    memcpy(&ua, &ha, 2); memcpy(&ub, &hb, 2);
    return (uint32_t)ua | ((uint32_t)ub << 16);
}

#define LDMX4(r0, r1, r2, r3, addr)                                            \
    asm volatile("ldmatrix.sync.aligned.m8n8.x4.shared.b16 {%0,%1,%2,%3}, [%4];" \
                 : "=r"(r0), "=r"(r1), "=r"(r2), "=r"(r3) : "r"(addr))

__device__ __forceinline__ void mma16816(float* c, const uint32_t* a, const uint32_t* b) {
    asm volatile(
        "mma.sync.aligned.m16n8k16.row.col.f32.f16.f16.f32 "
        "{%0,%1,%2,%3},{%4,%5,%6,%7},{%8,%9},{%0,%1,%2,%3};"
        : "+f"(c[0]), "+f"(c[1]), "+f"(c[2]), "+f"(c[3])
        : "r"(a[0]), "r"(a[1]), "r"(a[2]), "r"(a[3]), "r"(b[0]), "r"(b[1]));
}
__device__ __forceinline__ void cp16(uint32_t dst, const void* src) {
    asm volatile("cp.async.cg.shared.global [%0], [%1], 16;" :: "r"(dst), "l"(src));
}

// ===========================================================================
// preprocessing
// ===========================================================================
// Wo -> wo_h (hi only, row-major)
__global__ void split_wo_k(const float* __restrict__ Wo, __half* __restrict__ wo_h, long n4) {
    long i = (long)blockIdx.x * blockDim.x + threadIdx.x;
    if (i >= n4) return;
    float4 v = ((const float4*)Wo)[i];
    ((uint2*)wo_h)[i] = make_uint2(pack2(v.x, v.y), pack2(v.z, v.w));
}

// fused x preprocessing (x read exactly once):
//   xs_h[r][c] = hi(x[r][c]) ; xt_h[c][r] ; colsum tile-partials part_cs
__global__ void xsplit_k(const float* __restrict__ x, long sIn,
                         __half* __restrict__ xs_h, long sXs,
                         __half* __restrict__ xt_h, long sXt,
                         float* __restrict__ part_cs) {
    __shared__ float t[32][33];
    __shared__ float red[8][33];
    int b = blockIdx.z;
    x    += (long)b * sIn;
    xs_h += (long)b * sXs;
    xt_h += (long)b * sXt;
    int c0 = blockIdx.x * 32, r0 = blockIdx.y * 32;
    int tx = threadIdx.x, ty = threadIdx.y;  // (32,8)
    float cs = 0.f;
#pragma unroll
    for (int i = 0; i < 4; i++) {
        int rr = r0 + ty + i * 8;
        float v = x[(long)rr * Ed + c0 + tx];
        t[ty + i * 8][tx] = v;
        cs += v;
        xs_h[(long)rr * Ed + c0 + tx] = __float2half_rn(v);
    }
    red[ty][tx] = cs;
    __syncthreads();
#pragma unroll
    for (int i = 0; i < 4; i++) {
        float v = t[tx][ty + i * 8];
        xt_h[(long)(c0 + ty + i * 8) * Sd + r0 + tx] = __float2half_rn(v);
    }
    if (ty == 0) {
        float v = 0.f;
#pragma unroll
        for (int k = 0; k < 8; k++) v += red[k][tx];
        part_cs[((long)b * CS + blockIdx.y) * Ed + c0 + tx] = v;
    }
}

// z=0: Wq^T ; z=1: Wk^T ; z=2: Wv^T   (hi only)
__global__ void tsplitW_k(const float* __restrict__ Wq, const float* __restrict__ Wk,
                          const float* __restrict__ Wv,
                          __half* __restrict__ wqt_h,
                          __half* __restrict__ wkt_h, __half* __restrict__ wvt_h) {
    const float* in; __half* oh;
    if (blockIdx.z == 0)      { in = Wq; oh = wqt_h; }
    else if (blockIdx.z == 1) { in = Wk; oh = wkt_h; }
    else                      { in = Wv; oh = wvt_h; }
    __shared__ float t[32][33];
    int c0 = blockIdx.x * 32, r0 = blockIdx.y * 32;
    int tx = threadIdx.x, ty = threadIdx.y;
#pragma unroll
    for (int i = 0; i < 4; i++)
        t[ty + i * 8][tx] = in[(long)(r0 + ty + i * 8) * Ed + c0 + tx];
    __syncthreads();
#pragma unroll
    for (int i = 0; i < 4; i++)
        oh[(long)(c0 + ty + i * 8) * Ed + r0 + tx] =
            __float2half_rn(t[tx][ty + i * 8]);
}

// mirror upper-triangle tiles of symmetric fp16 matrix into lower triangle
__global__ void mirror_k(__half* __restrict__ Gh, long sEE) {
    int bi = blockIdx.y, bj = blockIdx.x;
    if (bi > bj) return;
    __half* G = Gh + (long)blockIdx.z * sEE;
    __shared__ uint16_t t[32][33];
    int tx = threadIdx.x, ty = threadIdx.y;
    int r0 = bi * 32, c0 = bj * 32;
#pragma unroll
    for (int i = 0; i < 4; i++) {
        int r = ty + i * 8;
        uint16_t v;
        memcpy(&v, &G[(long)(r0 + r) * Ed + c0 + tx], 2);
        t[r][tx] = v;
    }
    __syncthreads();
#pragma unroll
    for (int i = 0; i < 4; i++) {
        int rr = ty + i * 8;
        int cc = tx;
        int dr = c0 + rr, dc = r0 + cc;
        if (dr > dc) {
            uint16_t v = t[cc][rr];
            memcpy(&G[(long)dr * Ed + dc], &v, 2);
        }
    }
}

// ===========================================================================
// split-K matvec engine
// ===========================================================================
// weight jobs: z=0: Wq^T bk ; z=1: Wk^T bq
__global__ void mv1_part_k(const float* __restrict__ Wq, const float* __restrict__ bk,
                           const float* __restrict__ Wk, const float* __restrict__ bq,
                           float* __restrict__ part) {
    int z = blockIdx.z;
    const float* A = z ? Wk : Wq;
    const float* w = z ? bq : bk;
    int j = blockIdx.x * 256 + threadIdx.x;
    int chunk = Ed / KS;
    int r0 = blockIdx.y * chunk;
    float a0 = 0.f, a1 = 0.f;
    for (int i = 0; i < chunk; i += 2) {
        a0 += A[(long)(r0 + i) * Ed + j] * w[r0 + i];
        a1 += A[(long)(r0 + i + 1) * Ed + j] * w[r0 + i + 1];
    }
    part[((long)z * KS + blockIdx.y) * Ed + j] = a0 + a1;
}

// z=0: u2 ; z=1: t1 (KS partials) ; z=2..5: s_b (CS partials from part_cs)
__global__ void red1_k(const float* __restrict__ part, const float* __restrict__ part_cs,
                       float* __restrict__ u2, float* __restrict__ t1,
                       float* __restrict__ s) {
    int z = blockIdx.y;
    int j = blockIdx.x * 256 + threadIdx.x;
    float a = 0.f;
    if (z < 2) {
#pragma unroll
        for (int ks = 0; ks < KS; ks++) a += part[((long)z * KS + ks) * Ed + j];
        (z ? t1 : u2)[j] = a;
    } else {
        int b = z - 2;
#pragma unroll
        for (int k = 0; k < CS; k++) a += part_cs[((long)b * CS + k) * Ed + j];
        s[(long)b * Ed + j] = a;
    }
}

// phase 2: u1_b = Wq^T p_b (4 jobs)
__global__ void mv2_part_k(const float* __restrict__ Wq, const float* __restrict__ p,
                           float* __restrict__ part) {
    int b = blockIdx.z;
    const float* w = p + (long)b * Ed;
    int j = blockIdx.x * 256 + threadIdx.x;
    int chunk = Ed / KS;
    int r0 = blockIdx.y * chunk;
    float a0 = 0.f, a1 = 0.f;
    for (int i = 0; i < chunk; i += 2) {
        a0 += Wq[(long)(r0 + i) * Ed + j] * w[r0 + i];
        a1 += Wq[(long)(r0 + i + 1) * Ed + j] * w[r0 + i + 1];
    }
    part[((long)b * KS + blockIdx.y) * Ed + j] = a0 + a1;
}

__global__ void mv2_red_k(const float* __restrict__ part, float* __restrict__ u1) {
    int b = blockIdx.y;
    int j = blockIdx.x * 256 + threadIdx.x;
    float a = 0.f;
#pragma unroll
    for (int ks = 0; ks < KS; ks++) a += part[((long)b * KS + ks) * Ed + j];
    u1[(long)b * Ed + j] = a;
}

// ===========================================================================
// rowdot-shaped vector kernels
// ===========================================================================
// z=0: p_b = Wk s_b ; z=1: r_b = Wv s_b ; z=2 (b==0): w1 = Wo bv
__global__ void rowdot_prw_k(const float* __restrict__ Wk, const float* __restrict__ Wv,
                             const float* __restrict__ Wo,
                             const float* __restrict__ s, const float* __restrict__ bv,
                             float* __restrict__ p, float* __restrict__ r,
                             float* __restrict__ w1) {
    int z = blockIdx.z, b = blockIdx.y;
    const float* A; const float* xv; float* y;
    if (z == 0)      { A = Wk; xv = s + (long)b * Ed; y = p + (long)b * Ed; }
    else if (z == 1) { A = Wv; xv = s + (long)b * Ed; y = r + (long)b * Ed; }
    else             { if (b) return; A = Wo; xv = bv; y = w1; }
    int warp = blockIdx.x * 8 + (threadIdx.x >> 5);
    int lane = threadIdx.x & 31;
    const float* row = A + (long)warp * Ed;
    float acc = 0.f;
    for (int j = lane; j < Ed; j += 32) acc += row[j] * xv[j];
#pragma unroll
    for (int o = 16; o > 0; o >>= 1) acc += __shfl_xor_sync(0xffffffffu, acc, o);
    if (lane == 0) y[warp] = acc;
}

// z=0: w2_b = Wo r_b ; z=1 (b==0): dp[bid]=p_bid.bq (bid<Bd), db=bk.bq (bid=Bd)
__global__ void w2dots_k(const float* __restrict__ Wo, const float* __restrict__ r,
                         const float* __restrict__ p, const float* __restrict__ bk,
                         const float* __restrict__ bq,
                         float* __restrict__ w2, float* __restrict__ dp,
                         float* __restrict__ db) {
    int z = blockIdx.z, b = blockIdx.y;
    if (z == 0) {
        int warp = blockIdx.x * 8 + (threadIdx.x >> 5);
        int lane = threadIdx.x & 31;
        const float* xv = r + (long)b * Ed;
        const float* row = Wo + (long)warp * Ed;
        float acc = 0.f;
        for (int j = lane; j < Ed; j += 32) acc += row[j] * xv[j];
#pragma unroll
        for (int o = 16; o > 0; o >>= 1) acc += __shfl_xor_sync(0xffffffffu, acc, o);
        if (lane == 0) w2[(long)b * Ed + warp] = acc;
    } else {
        if (b != 0) return;
        int bid = blockIdx.x;
        if (bid > Bd) return;
        const float* a = (bid < Bd) ? p + (long)bid * Ed : bk;
        __shared__ float red[8];
        int tid = threadIdx.x;
        float acc = 0.f;
        for (int j = tid; j < Ed; j += 256) acc += a[j] * bq[j];
#pragma unroll
        for (int o = 16; o > 0; o >>= 1) acc += __shfl_xor_sync(0xffffffffu, acc, o);
        if ((tid & 31) == 0) red[tid >> 5] = acc;
        __syncthreads();
        if (tid < 8) {
            float v = red[tid];
#pragma unroll
            for (int o = 4; o > 0; o >>= 1) v += __shfl_xor_sync(0xffu, v, o);
            if (tid == 0) { if (bid < Bd) dp[bid] = v; else db[0] = v; }
        }
    }
}

// t2_b[i] = dot(G_h[i,:], t1)
__global__ void rowdot_hf_k(const __half* __restrict__ Ah, long sA,
                            const float* __restrict__ xv,
                            float* __restrict__ y, int cols) {
    Ah += (long)blockIdx.y * sA;
    y  += blockIdx.y * cols;
    int warp = blockIdx.x * 8 + (threadIdx.x >> 5);
    int lane = threadIdx.x & 31;
    const __half* rh = Ah + (long)warp * cols;
    float acc = 0.f;
    for (int j = lane; j < cols; j += 32) acc += __half2float(rh[j]) * xv[j];
#pragma unroll
    for (int o = 16; o > 0; o >>= 1) acc += __shfl_xor_sync(0xffffffffu, acc, o);
    if (lane == 0) y[warp] = acc;
}

// d_b[i] = (Wv t2_b)[i] + bv[i]*(dp[b] + S*db) + r_b[i]*db
__global__ void dfin_k(const float* __restrict__ Wv, const float* __restrict__ t2,
                       const float* __restrict__ bv, const float* __restrict__ r,
                       const float* __restrict__ dp, const float* __restrict__ db,
                       float* __restrict__ d) {
    int b = blockIdx.y;
    int warp = blockIdx.x * 8 + (threadIdx.x >> 5);
    int lane = threadIdx.x & 31;
    const float* xv = t2 + (long)b * Ed;
    const float* row = Wv + (long)warp * Ed;
    float acc = 0.f;
    for (int j = lane; j < Ed; j += 32) acc += row[j] * xv[j];
#pragma unroll
    for (int o = 16; o > 0; o >>= 1) acc += __shfl_xor_sync(0xffffffffu, acc, o);
    if (lane == 0) {
        float dbv = db[0];
        d[(long)b * Ed + warp] = acc + bv[warp] * (dp[b] + (float)Sd * dbv)
                               + r[(long)b * Ed + warp] * dbv;
    }
}

// cb_b = SCALE * Wo d_b + bo
__global__ void rowdot_k(const float* __restrict__ A,
                         const float* __restrict__ xv, int sxv,
                         const float* __restrict__ bias,
                         float* __restrict__ y, int sy, int cols, float alpha) {
    xv += blockIdx.y * sxv;
    y  += blockIdx.y * sy;
    int warp = blockIdx.x * 8 + (threadIdx.x >> 5);
    int lane = threadIdx.x & 31;
    const float* row = A + (long)warp * cols;
    float acc = 0.f;
    for (int j = lane; j < cols; j += 32) acc += row[j] * xv[j];
#pragma unroll
    for (int o = 16; o > 0; o >>= 1) acc += __shfl_xor_sync(0xffffffffu, acc, o);
    if (lane == 0) y[warp] = alpha * acc + (bias ? bias[warp] : 0.f);
}

// ===========================================================================
// fp16 1-product GEMM engine: C = alpha * A_hi B_hi^T [+ epilogue]
//   512 threads (16 warps 4x4), warp tile 32x32, block 128x128, K-chunk 64,
//   4-stage cp.async pipeline (32KB/stage).
// ===========================================================================
constexpr int OFF_A = 0;
constexpr int OFF_B = 16384;
constexpr int STAGE = 32768;
constexpr int DYN_SMEM = 4 * STAGE;  // 128 KB

__device__ __forceinline__ void issue_tile(uint32_t sdst, const __half* g,
                                           long ldK, int tid) {
#pragma unroll
    for (int i = 0; i < 2; i++) {
        int gi = tid + i * 512;
        int row = gi >> 3, c16 = gi & 7;
        uint32_t off = SWZ128((uint32_t)(row * 128 + c16 * 16));
        cp16(sdst + off, (const char*)(g + (long)row * ldK) + c16 * 16);
    }
}

__device__ __forceinline__ void compute_ks(uint32_t sb, int ks, int mw, int nw,
                                           int lane, float (&acc)[2][4][4]) {
    const uint32_t rowsel = lane & 15;
    const uint32_t ksel = (lane >> 4) * 16;
    uint32_t ah[2][4];
#pragma unroll
    for (int mt = 0; mt < 2; mt++) {
        uint32_t off = SWZ128((uint32_t)((mw + mt * 16 + rowsel) * 128 + ks * 32 + ksel));
        LDMX4(ah[mt][0], ah[mt][1], ah[mt][2], ah[mt][3], sb + OFF_A + off);
    }
    uint32_t bh[4][2];
#pragma unroll
    for (int nt = 0; nt < 2; nt++) {
        uint32_t off = SWZ128((uint32_t)((nw + nt * 16 + rowsel) * 128 + ks * 32 + ksel));
        uint32_t r0, r1, r2, r3;
        LDMX4(r0, r1, r2, r3, sb + OFF_B + off);
        bh[2 * nt][0] = r0; bh[2 * nt][1] = r2;
        bh[2 * nt + 1][0] = r1; bh[2 * nt + 1][1] = r3;
    }
#pragma unroll
    for (int mt = 0; mt < 2; mt++)
#pragma unroll
        for (int nf = 0; nf < 4; nf++)
            mma16816(acc[mt][nf], ah[mt], bh[nf]);
}

__global__ void __launch_bounds__(512, 1) hf_gemm(
    const __half* __restrict__ Ah, long sA,
    const __half* __restrict__ Bh, long sB,
    float* __restrict__ Cf, long sCf,
    __half* __restrict__ Ch, long sCb,
    int Nd, int Kd, float alpha, int mode, int tri, int dual,
    const __half* __restrict__ A2h, const __half* __restrict__ B2h,
    __half* __restrict__ C2h,
    const float* __restrict__ v1, int sv1, const float* __restrict__ v2,
    const float* __restrict__ v3, const float* __restrict__ v4, int sv4, float rk)
{
    extern __shared__ char smem[];
    const int bz = blockIdx.z;
    if (dual && bz == 1) {
        Ah = A2h; Bh = B2h; Ch = C2h;
    } else {
        Ah += (long)bz * sA;
        Bh += (long)bz * sB;
        if (Cf) Cf += (long)bz * sCf;
        if (Ch) Ch += (long)bz * sCb;
        if (v1) v1 += (long)bz * sv1;
        if (v4) v4 += (long)bz * sv4;
    }

    int m0, n0;
    if (tri) {
        int t = blockIdx.x, ti = 0;
        while (t >= 8 - ti) { t -= 8 - ti; ti++; }
        m0 = ti * 128;
        n0 = (ti + t) * 128;
    } else {
        m0 = blockIdx.y * 128;
        n0 = blockIdx.x * 128;
    }
    const int tid = threadIdx.x;
    const int lane = tid & 31;
    const int wid = tid >> 5;
    const int mw = (wid >> 2) * 32;
    const int nw = (wid & 3) * 32;
    const uint32_t sbase = smem_u32(smem);

    float acc[2][4][4];
#pragma unroll
    for (int mt = 0; mt < 2; mt++)
#pragma unroll
        for (int nf = 0; nf < 4; nf++)
#pragma unroll
            for (int q = 0; q < 4; q++) acc[mt][nf][q] = 0.f;

    const int nCh = Kd / 64;
    auto issue = [&](int c) {
        uint32_t sb = sbase + (uint32_t)(c & 3) * STAGE;
        long k0 = (long)c * 64;
        issue_tile(sb + OFF_A, Ah + (long)m0 * Kd + k0, Kd, tid);
        issue_tile(sb + OFF_B, Bh + (long)n0 * Kd + k0, Kd, tid);
        asm volatile("cp.async.commit_group;" ::: "memory");
    };

    issue(0); issue(1); issue(2);
    for (int c = 0; c < nCh; c++) {
        if (c + 3 <= nCh) {
            asm volatile("cp.async.wait_group 2;" ::: "memory");
        } else if (c + 2 == nCh) {
            asm volatile("cp.async.wait_group 1;" ::: "memory");
        } else {
            asm volatile("cp.async.wait_group 0;" ::: "memory");
        }
        __syncthreads();
        if (c + 3 < nCh) issue(c + 3);
        const uint32_t sb = sbase + (uint32_t)(c & 3) * STAGE;
        compute_ks(sb, 0, mw, nw, lane, acc);
        compute_ks(sb, 1, mw, nw, lane, acc);
        compute_ks(sb, 2, mw, nw, lane, acc);
        compute_ks(sb, 3, mw, nw, lane, acc);
    }
    __syncthreads();

    // epilogue
    const int r = lane >> 2;
    const int cp = (lane & 3) * 2;
#pragma unroll
    for (int mt = 0; mt < 2; mt++)
#pragma unroll
        for (int rr = 0; rr < 2; rr++) {
            const int m = m0 + mw + mt * 16 + r + rr * 8;
            float pv = 0.f, bkv = 0.f;
            if (mode == 1) { pv = v1[m]; bkv = v3[m]; }
#pragma unroll
            for (int nf = 0; nf < 4; nf++) {
                const int nloc = nf * 8 + cp;
                const int n = n0 + nw + nloc;
                float f0 = alpha * acc[mt][nf][rr * 2 + 0];
                float f1 = alpha * acc[mt][nf][rr * 2 + 1];
                if (mode == 1) {
                    f0 += pv * v2[n + 0] + bkv * (v4[n + 0] + rk * v2[n + 0]);
                    f1 += pv * v2[n + 1] + bkv * (v4[n + 1] + rk * v2[n + 1]);
                } else if (mode == 2) {
                    f0 += v1[n + 0];
                    f1 += v1[n + 1];
                }
                long co = (long)m * Nd + n;
                if (Cf) *(float2*)(Cf + co) = make_float2(f0, f1);
                if (Ch) *(uint32_t*)(Ch + co) = pack2(f0, f1);
            }
        }
}

// ===========================================================================
// Launch — single stream; 1-product engine, hi limbs only.
// ===========================================================================
extern "C" void kernel_launch(void* const* d_in, const int* in_sizes, int n_in,
                              void* d_out, int out_size)
{
    const float* x  = (const float*)d_in[0];
    const float* Wq = (const float*)d_in[1];
    const float* bq = (const float*)d_in[2];
    const float* Wk = (const float*)d_in[3];
    const float* bk = (const float*)d_in[4];
    const float* Wv = (const float*)d_in[5];
    const float* bv = (const float*)d_in[6];
    const float* Wo = (const float*)d_in[7];
    const float* bo = (const float*)d_in[8];
    float* out = (float*)d_out;

    char* scr = nullptr;
    cudaGetSymbolAddress((void**)&scr, g_scratch);
    auto HF = [&](long off) { return (__half*)(scr + off); };

    __half *xs_h = HF(OFF_XS_H);
    __half *xt_h = HF(OFF_XT_H);
    __half *wqt_h = HF(OFF_WQT_H);
    __half *wkt_h = HF(OFF_WKT_H);
    __half *wvt_h = HF(OFF_WVT_H);
    __half *wo_h  = HF(OFF_WO_H);
    __half *P_h = HF(OFF_P_H);
    __half *Q_h = HF(OFF_Q_H);
    __half *G_h = HF(OFF_G_H);
    __half *R_h = HF(OFF_R_H);
    __half *UT_h = HF(OFF_UT_H);

    float* vec = (float*)(scr + OFF_VEC);
    float* s    = vec;                 // [B][E]
    float* p    = s    + Bd * Ed;
    float* r    = p    + Bd * Ed;
    float* u1   = r    + Bd * Ed;
    float* w2   = u1   + Bd * Ed;
    float* t2   = w2   + Bd * Ed;
    float* d    = t2   + Bd * Ed;
    float* cb   = d    + Bd * Ed;
    float* u2   = cb   + Bd * Ed;      // [E]
    float* w1   = u2   + Ed;
    float* t1   = w1   + Ed;
    float* dp   = t1   + Ed;           // [B]
    float* db   = dp   + Bd;           // [1]
    float* part = db + 256;            // weight matvec partials (<=128K floats)
    float* part_cs = part + 4 * KS * Ed;  // colsum tile partials (B*CS*Ed = 256K floats)

    const long sX = (long)Sd * Ed;     // 2M elems
    const long sXT = (long)Ed * Sd;
    const long sEE = (long)Ed * Ed;

    cudaFuncSetAttribute(hf_gemm, cudaFuncAttributeMaxDynamicSharedMemorySize, DYN_SMEM);
    dim3 blk(512);

    // ---- preprocessing (3 launches; x read exactly once, colsum fused) ----
    xsplit_k<<<dim3(Ed / 32, Sd / 32, Bd), dim3(32, 8)>>>(x, sX, xs_h, sX, xt_h, sXT, part_cs);
    tsplitW_k<<<dim3(32, 32, 3), dim3(32, 8)>>>(Wq, Wk, Wv, wqt_h, wkt_h, wvt_h);
    split_wo_k<<<sEE / 4 / 256, 256>>>(Wo, wo_h, sEE / 4);

    // ---- vectors ----
    mv1_part_k<<<dim3(Ed / 256, KS, 2), 256>>>(Wq, bk, Wk, bq, part);
    red1_k<<<dim3(Ed / 256, 6), 256>>>(part, part_cs, u2, t1, s);
    rowdot_prw_k<<<dim3(Ed / 8, Bd, 3), 256>>>(Wk, Wv, Wo, s, bv, p, r, w1);
    mv2_part_k<<<dim3(Ed / 256, KS, Bd), 256>>>(Wq, p, part);
    mv2_red_k<<<dim3(Ed / 256, Bd), 256>>>(part, u1);
    w2dots_k<<<dim3(Ed / 8, Bd, 2), 256>>>(Wo, r, p, bk, bq, w2, dp, db);

    // ---- GEMMs + cb chain ----
    // merged: z=0 -> P = Wq^T Wk ; z=1 -> Q = Wo Wv
    hf_gemm<<<dim3(8, 8, 2), blk, DYN_SMEM>>>(wqt_h, 0, wkt_h, 0,
        nullptr, 0, P_h, 0, Ed, Ed, 1.f, 0, 0, 1,
        wo_h, wvt_h, Q_h,
        nullptr, 0, nullptr, nullptr, nullptr, 0, 0.f);
    // G_b = x^T x : upper-triangle tiles (36) per batch, K=S
    hf_gemm<<<dim3(36, 1, Bd), blk, DYN_SMEM>>>(xt_h, sXT, xt_h, sXT,
        nullptr, 0, G_h, sEE, Ed, Sd, 1.f, 0, 1, 0,
        nullptr, nullptr, nullptr,
        nullptr, 0, nullptr, nullptr, nullptr, 0, 0.f);
    mirror_k<<<dim3(Ed / 32, Ed / 32, Bd), dim3(32, 8)>>>(G_h, sEE);

    // cb chain (3 launches)
    rowdot_hf_k<<<dim3(Ed / 8, Bd), 256>>>(G_h, sEE, t1, t2, Ed);
    dfin_k<<<dim3(Ed / 8, Bd), 256>>>(Wv, t2, bv, r, dp, db, d);
    rowdot_k<<<dim3(Ed / 8, Bd), 256>>>(Wo, d, Ed, bo, cb, Ed, Ed, SCALE_F);

    // R_b = Q G_b (G symmetric -> row-major as B ok)
    hf_gemm<<<dim3(8, 8, Bd), blk, DYN_SMEM>>>(Q_h, 0, G_h, sEE,
        nullptr, 0, R_h, sEE, Ed, Ed, 1.f, 0, 0, 0,
        nullptr, nullptr, nullptr,
        nullptr, 0, nullptr, nullptr, nullptr, 0, 0.f);
    // UT_b = R_b P^T + w2 u2^T + w1 (u1 + S u2)^T
    hf_gemm<<<dim3(8, 8, Bd), blk, DYN_SMEM>>>(R_h, sEE, P_h, 0,
        nullptr, 0, UT_h, sEE, Ed, Ed, 1.f, 1, 0, 0,
        nullptr, nullptr, nullptr,
        w2, Ed, u2, w1, u1, Ed, (float)Sd);
    // out_b = SCALE * x UT^T + c_b
    hf_gemm<<<dim3(8, 16, Bd), blk, DYN_SMEM>>>(xs_h, sX, UT_h, sEE,
        out, sX, nullptr, 0, Ed, Ed, SCALE_F, 2, 0, 0,
        nullptr, nullptr, nullptr,
        cb, Ed, nullptr, nullptr, nullptr, 0, 0.f);
}

// round 14
// speedup vs baseline: 2.7507x; 1.0344x over previous
#include <cuda_runtime.h>
#include <cuda_fp16.h>
#include <cstdint>
#include <cstring>

// Problem dims (fixed by setup_inputs)
constexpr int Bd = 4;
constexpr int Sd = 2048;
constexpr int Ed = 1024;
constexpr float SCALE_F = 0.125f;
constexpr int KS = 32;       // split-K factor for mv2
constexpr int KSW = 32;      // row-tile partials from tsplitW (Ed/32)
constexpr int CS = Sd / 32;  // 64 colsum tile-partials per batch

// ===========================================================================
// scratch layout (bytes) — fp16 hi-limb arrays only (1-product engine)
// ===========================================================================
constexpr long MB = 1024 * 1024;
constexpr long OFF_XS_H = 0;          // x hi   [B][S][E]  16MB
constexpr long OFF_XT_H = 32 * MB;    // x^T hi [B][E][S]  16MB
constexpr long OFF_WQT_H = 64 * MB;   // Wq^T hi [E][E]     2MB
constexpr long OFF_WKT_H = 68 * MB;
constexpr long OFF_WVT_H = 72 * MB;
constexpr long OFF_WO_H  = 76 * MB;   // Wo hi (no transpose)
constexpr long OFF_P_H   = 80 * MB;   // P = Wq^T Wk
constexpr long OFF_Q_H   = 84 * MB;   // Q = Wo Wv
constexpr long OFF_G_H   = 88 * MB;   // G  [B][E][E]  8MB
constexpr long OFF_R_H   = 104 * MB;  // R = Q G
constexpr long OFF_UT_H  = 120 * MB;  // U^T
constexpr long OFF_VEC   = 130 * MB;  // fp32 vectors + partials
constexpr long SCRATCH_BYTES = 136 * MB;

__device__ __align__(1024) char g_scratch[SCRATCH_BYTES];

// ===========================================================================
// helpers
// ===========================================================================
__device__ __forceinline__ uint32_t smem_u32(const void* p) {
    uint32_t a;
    asm("{ .reg .u64 t; cvta.to.shared.u64 t, %1; cvt.u32.u64 %0, t; }" : "=r"(a) : "l"(p));
    return a;
}
#define SWZ128(o) ((o) ^ (((o) >> 3) & 0x70))

__device__ __forceinline__ uint32_t pack2(float a, float b) {
    __half ha = __float2half_rn(a), hb = __float2half_rn(b);
    uint16_t ua, ub;
    memcpy(&ua, &ha, 2); memcpy(&ub, &hb, 2);
    return (uint32_t)ua | ((uint32_t)ub << 16);
}

#define LDMX4(r0, r1, r2, r3, addr)                                            \
    asm volatile("ldmatrix.sync.aligned.m8n8.x4.shared.b16 {%0,%1,%2,%3}, [%4];" \
                 : "=r"(r0), "=r"(r1), "=r"(r2), "=r"(r3) : "r"(addr))

__device__ __forceinline__ void mma16816(float* c, const uint32_t* a, const uint32_t* b) {
    asm volatile(
        "mma.sync.aligned.m16n8k16.row.col.f32.f16.f16.f32 "
        "{%0,%1,%2,%3},{%4,%5,%6,%7},{%8,%9},{%0,%1,%2,%3};"
        : "+f"(c[0]), "+f"(c[1]), "+f"(c[2]), "+f"(c[3])
        : "r"(a[0]), "r"(a[1]), "r"(a[2]), "r"(a[3]), "r"(b[0]), "r"(b[1]));
}
__device__ __forceinline__ void cp16(uint32_t dst, const void* src) {
    asm volatile("cp.async.cg.shared.global [%0], [%1], 16;" :: "r"(dst), "l"(src));
}

// ===========================================================================
// preprocessing
// ===========================================================================
// Wo -> wo_h (hi only, row-major)
__global__ void split_wo_k(const float* __restrict__ Wo, __half* __restrict__ wo_h, long n4) {
    long i = (long)blockIdx.x * blockDim.x + threadIdx.x;
    if (i >= n4) return;
    float4 v = ((const float4*)Wo)[i];
    ((uint2*)wo_h)[i] = make_uint2(pack2(v.x, v.y), pack2(v.z, v.w));
}

// fused x preprocessing (x read exactly once):
//   xs_h[r][c] = hi(x[r][c]) ; xt_h[c][r] ; colsum tile-partials part_cs
__global__ void xsplit_k(const float* __restrict__ x, long sIn,
                         __half* __restrict__ xs_h, long sXs,
                         __half* __restrict__ xt_h, long sXt,
                         float* __restrict__ part_cs) {
    __shared__ float t[32][33];
    __shared__ float red[8][33];
    int b = blockIdx.z;
    x    += (long)b * sIn;
    xs_h += (long)b * sXs;
    xt_h += (long)b * sXt;
    int c0 = blockIdx.x * 32, r0 = blockIdx.y * 32;
    int tx = threadIdx.x, ty = threadIdx.y;  // (32,8)
    float cs = 0.f;
#pragma unroll
    for (int i = 0; i < 4; i++) {
        int rr = r0 + ty + i * 8;
        float v = x[(long)rr * Ed + c0 + tx];
        t[ty + i * 8][tx] = v;
        cs += v;
        xs_h[(long)rr * Ed + c0 + tx] = __float2half_rn(v);
    }
    red[ty][tx] = cs;
    __syncthreads();
#pragma unroll
    for (int i = 0; i < 4; i++) {
        float v = t[tx][ty + i * 8];
        xt_h[(long)(c0 + ty + i * 8) * Sd + r0 + tx] = __float2half_rn(v);
    }
    if (ty == 0) {
        float v = 0.f;
#pragma unroll
        for (int k = 0; k < 8; k++) v += red[k][tx];
        part_cs[((long)b * CS + blockIdx.y) * Ed + c0 + tx] = v;
    }
}

// z=0: Wq^T (+ u2 partials with bk) ; z=1: Wk^T (+ t1 partials with bq) ;
// z=2: Wv^T (no partials). Fuses the old mv1 matvec into the transpose pass.
__global__ void tsplitW_k(const float* __restrict__ Wq, const float* __restrict__ Wk,
                          const float* __restrict__ Wv,
                          const float* __restrict__ bk, const float* __restrict__ bq,
                          __half* __restrict__ wqt_h,
                          __half* __restrict__ wkt_h, __half* __restrict__ wvt_h,
                          float* __restrict__ part_w) {
    int z = blockIdx.z;
    const float* in; __half* oh; const float* w;
    if (z == 0)      { in = Wq; oh = wqt_h; w = bk; }
    else if (z == 1) { in = Wk; oh = wkt_h; w = bq; }
    else             { in = Wv; oh = wvt_h; w = nullptr; }
    __shared__ float t[32][33];
    __shared__ float red[8][33];
    int c0 = blockIdx.x * 32, r0 = blockIdx.y * 32;
    int tx = threadIdx.x, ty = threadIdx.y;
    float pw = 0.f;
#pragma unroll
    for (int i = 0; i < 4; i++) {
        int rr = r0 + ty + i * 8;
        float v = in[(long)rr * Ed + c0 + tx];
        t[ty + i * 8][tx] = v;
        if (w) pw += v * w[rr];
    }
    if (w) red[ty][tx] = pw;
    __syncthreads();
#pragma unroll
    for (int i = 0; i < 4; i++)
        oh[(long)(c0 + ty + i * 8) * Ed + r0 + tx] =
            __float2half_rn(t[tx][ty + i * 8]);
    if (w && ty == 0) {
        float v = 0.f;
#pragma unroll
        for (int k = 0; k < 8; k++) v += red[k][tx];
        part_w[((long)z * KSW + blockIdx.y) * Ed + c0 + tx] = v;
    }
}

// mirror upper-triangle tiles of symmetric fp16 matrix into lower triangle
__global__ void mirror_k(__half* __restrict__ Gh, long sEE) {
    int bi = blockIdx.y, bj = blockIdx.x;
    if (bi > bj) return;
    __half* G = Gh + (long)blockIdx.z * sEE;
    __shared__ uint16_t t[32][33];
    int tx = threadIdx.x, ty = threadIdx.y;
    int r0 = bi * 32, c0 = bj * 32;
#pragma unroll
    for (int i = 0; i < 4; i++) {
        int r = ty + i * 8;
        uint16_t v;
        memcpy(&v, &G[(long)(r0 + r) * Ed + c0 + tx], 2);
        t[r][tx] = v;
    }
    __syncthreads();
#pragma unroll
    for (int i = 0; i < 4; i++) {
        int rr = ty + i * 8;
        int cc = tx;
        int dr = c0 + rr, dc = r0 + cc;
        if (dr > dc) {
            uint16_t v = t[cc][rr];
            memcpy(&G[(long)dr * Ed + dc], &v, 2);
        }
    }
}

// ===========================================================================
// vector kernels
// ===========================================================================
// z=0: u2 ; z=1: t1 (KSW partials from tsplitW) ; z=2..5: s_b (CS partials)
__global__ void red1_k(const float* __restrict__ part_w, const float* __restrict__ part_cs,
                       float* __restrict__ u2, float* __restrict__ t1,
                       float* __restrict__ s) {
    int z = blockIdx.y;
    int j = blockIdx.x * 256 + threadIdx.x;
    float a = 0.f;
    if (z < 2) {
#pragma unroll
        for (int k = 0; k < KSW; k++) a += part_w[((long)z * KSW + k) * Ed + j];
        (z ? t1 : u2)[j] = a;
    } else {
        int b = z - 2;
#pragma unroll
        for (int k = 0; k < CS; k++) a += part_cs[((long)b * CS + k) * Ed + j];
        s[(long)b * Ed + j] = a;
    }
}

// z=0: p_b = Wk s_b ; z=1: r_b = Wv s_b ; z=2 (b==0): w1 = Wo bv
__global__ void rowdot_prw_k(const float* __restrict__ Wk, const float* __restrict__ Wv,
                             const float* __restrict__ Wo,
                             const float* __restrict__ s, const float* __restrict__ bv,
                             float* __restrict__ p, float* __restrict__ r,
                             float* __restrict__ w1) {
    int z = blockIdx.z, b = blockIdx.y;
    const float* A; const float* xv; float* y;
    if (z == 0)      { A = Wk; xv = s + (long)b * Ed; y = p + (long)b * Ed; }
    else if (z == 1) { A = Wv; xv = s + (long)b * Ed; y = r + (long)b * Ed; }
    else             { if (b) return; A = Wo; xv = bv; y = w1; }
    int warp = blockIdx.x * 8 + (threadIdx.x >> 5);
    int lane = threadIdx.x & 31;
    const float* row = A + (long)warp * Ed;
    float acc = 0.f;
    for (int j = lane; j < Ed; j += 32) acc += row[j] * xv[j];
#pragma unroll
    for (int o = 16; o > 0; o >>= 1) acc += __shfl_xor_sync(0xffffffffu, acc, o);
    if (lane == 0) y[warp] = acc;
}

// u1_b = Wq^T p_b split-K partials (4 jobs)
__global__ void mv2_part_k(const float* __restrict__ Wq, const float* __restrict__ p,
                           float* __restrict__ part) {
    int b = blockIdx.z;
    const float* w = p + (long)b * Ed;
    int j = blockIdx.x * 256 + threadIdx.x;
    int chunk = Ed / KS;
    int r0 = blockIdx.y * chunk;
    float a0 = 0.f, a1 = 0.f;
    for (int i = 0; i < chunk; i += 2) {
        a0 += Wq[(long)(r0 + i) * Ed + j] * w[r0 + i];
        a1 += Wq[(long)(r0 + i + 1) * Ed + j] * w[r0 + i + 1];
    }
    part[((long)b * KS + blockIdx.y) * Ed + j] = a0 + a1;
}

// z=0: u1 reduce ; z=1: w2_b = Wo r_b ; z=2 (b==0): dp/db dots
__global__ void red2_k(const float* __restrict__ part,
                       const float* __restrict__ Wo, const float* __restrict__ r,
                       const float* __restrict__ p, const float* __restrict__ bk,
                       const float* __restrict__ bq,
                       float* __restrict__ u1, float* __restrict__ w2,
                       float* __restrict__ dp, float* __restrict__ db) {
    int z = blockIdx.z, b = blockIdx.y;
    if (z == 0) {
        if (blockIdx.x >= Ed / 256) return;
        int j = blockIdx.x * 256 + threadIdx.x;
        float a = 0.f;
#pragma unroll
        for (int ks = 0; ks < KS; ks++) a += part[((long)b * KS + ks) * Ed + j];
        u1[(long)b * Ed + j] = a;
    } else if (z == 1) {
        int warp = blockIdx.x * 8 + (threadIdx.x >> 5);
        int lane = threadIdx.x & 31;
        const float* xv = r + (long)b * Ed;
        const float* row = Wo + (long)warp * Ed;
        float acc = 0.f;
        for (int j = lane; j < Ed; j += 32) acc += row[j] * xv[j];
#pragma unroll
        for (int o = 16; o > 0; o >>= 1) acc += __shfl_xor_sync(0xffffffffu, acc, o);
        if (lane == 0) w2[(long)b * Ed + warp] = acc;
    } else {
        if (b != 0) return;
        int bid = blockIdx.x;
        if (bid > Bd) return;
        const float* a = (bid < Bd) ? p + (long)bid * Ed : bk;
        __shared__ float red[8];
        int tid = threadIdx.x;
        float acc = 0.f;
        for (int j = tid; j < Ed; j += 256) acc += a[j] * bq[j];
#pragma unroll
        for (int o = 16; o > 0; o >>= 1) acc += __shfl_xor_sync(0xffffffffu, acc, o);
        if ((tid & 31) == 0) red[tid >> 5] = acc;
        __syncthreads();
        if (tid < 8) {
            float v = red[tid];
#pragma unroll
            for (int o = 4; o > 0; o >>= 1) v += __shfl_xor_sync(0xffu, v, o);
            if (tid == 0) { if (bid < Bd) dp[bid] = v; else db[0] = v; }
        }
    }
}

// t2_b[i] = dot(G_h[i,:], t1)
__global__ void rowdot_hf_k(const __half* __restrict__ Ah, long sA,
                            const float* __restrict__ xv,
                            float* __restrict__ y, int cols) {
    Ah += (long)blockIdx.y * sA;
    y  += blockIdx.y * cols;
    int warp = blockIdx.x * 8 + (threadIdx.x >> 5);
    int lane = threadIdx.x & 31;
    const __half* rh = Ah + (long)warp * cols;
    float acc = 0.f;
    for (int j = lane; j < cols; j += 32) acc += __half2float(rh[j]) * xv[j];
#pragma unroll
    for (int o = 16; o > 0; o >>= 1) acc += __shfl_xor_sync(0xffffffffu, acc, o);
    if (lane == 0) y[warp] = acc;
}

// d_b[i] = (Wv t2_b)[i] + bv[i]*(dp[b] + S*db) + r_b[i]*db
__global__ void dfin_k(const float* __restrict__ Wv, const float* __restrict__ t2,
                       const float* __restrict__ bv, const float* __restrict__ r,
                       const float* __restrict__ dp, const float* __restrict__ db,
                       float* __restrict__ d) {
    int b = blockIdx.y;
    int warp = blockIdx.x * 8 + (threadIdx.x >> 5);
    int lane = threadIdx.x & 31;
    const float* xv = t2 + (long)b * Ed;
    const float* row = Wv + (long)warp * Ed;
    float acc = 0.f;
    for (int j = lane; j < Ed; j += 32) acc += row[j] * xv[j];
#pragma unroll
    for (int o = 16; o > 0; o >>= 1) acc += __shfl_xor_sync(0xffffffffu, acc, o);
    if (lane == 0) {
        float dbv = db[0];
        d[(long)b * Ed + warp] = acc + bv[warp] * (dp[b] + (float)Sd * dbv)
                               + r[(long)b * Ed + warp] * dbv;
    }
}

// cb_b = SCALE * Wo d_b + bo
__global__ void rowdot_k(const float* __restrict__ A,
                         const float* __restrict__ xv, int sxv,
                         const float* __restrict__ bias,
                         float* __restrict__ y, int sy, int cols, float alpha) {
    xv += blockIdx.y * sxv;
    y  += blockIdx.y * sy;
    int warp = blockIdx.x * 8 + (threadIdx.x >> 5);
    int lane = threadIdx.x & 31;
    const float* row = A + (long)warp * cols;
    float acc = 0.f;
    for (int j = lane; j < cols; j += 32) acc += row[j] * xv[j];
#pragma unroll
    for (int o = 16; o > 0; o >>= 1) acc += __shfl_xor_sync(0xffffffffu, acc, o);
    if (lane == 0) y[warp] = alpha * acc + (bias ? bias[warp] : 0.f);
}

// ===========================================================================
// fp16 1-product GEMM engine: C = alpha * A_hi B_hi^T [+ epilogue]
//   fuse mode: z<4 -> batched tri job (Kd) ; z=4 -> job2 (Kd2) ; z=5 -> job3 (Kd2)
// ===========================================================================
constexpr int OFF_A = 0;
constexpr int OFF_B = 16384;
constexpr int STAGE = 32768;
constexpr int DYN_SMEM = 4 * STAGE;  // 128 KB

__device__ __forceinline__ void issue_tile(uint32_t sdst, const __half* g,
                                           long ldK, int tid) {
#pragma unroll
    for (int i = 0; i < 2; i++) {
        int gi = tid + i * 512;
        int row = gi >> 3, c16 = gi & 7;
        uint32_t off = SWZ128((uint32_t)(row * 128 + c16 * 16));
        cp16(sdst + off, (const char*)(g + (long)row * ldK) + c16 * 16);
    }
}

__device__ __forceinline__ void compute_ks(uint32_t sb, int ks, int mw, int nw,
                                           int lane, float (&acc)[2][4][4]) {
    const uint32_t rowsel = lane & 15;
    const uint32_t ksel = (lane >> 4) * 16;
    uint32_t ah[2][4];
#pragma unroll
    for (int mt = 0; mt < 2; mt++) {
        uint32_t off = SWZ128((uint32_t)((mw + mt * 16 + rowsel) * 128 + ks * 32 + ksel));
        LDMX4(ah[mt][0], ah[mt][1], ah[mt][2], ah[mt][3], sb + OFF_A + off);
    }
    uint32_t bh[4][2];
#pragma unroll
    for (int nt = 0; nt < 2; nt++) {
        uint32_t off = SWZ128((uint32_t)((nw + nt * 16 + rowsel) * 128 + ks * 32 + ksel));
        uint32_t r0, r1, r2, r3;
        LDMX4(r0, r1, r2, r3, sb + OFF_B + off);
        bh[2 * nt][0] = r0; bh[2 * nt][1] = r2;
        bh[2 * nt + 1][0] = r1; bh[2 * nt + 1][1] = r3;
    }
#pragma unroll
    for (int mt = 0; mt < 2; mt++)
#pragma unroll
        for (int nf = 0; nf < 4; nf++)
            mma16816(acc[mt][nf], ah[mt], bh[nf]);
}

__global__ void __launch_bounds__(512, 1) hf_gemm(
    const __half* __restrict__ Ah, long sA,
    const __half* __restrict__ Bh, long sB,
    float* __restrict__ Cf, long sCf,
    __half* __restrict__ Ch, long sCb,
    int Nd, int Kd, float alpha, int mode, int tri, int fuse,
    const __half* __restrict__ A2h, const __half* __restrict__ B2h, __half* __restrict__ C2h,
    const __half* __restrict__ A3h, const __half* __restrict__ B3h, __half* __restrict__ C3h,
    int Kd2,
    const float* __restrict__ v1, int sv1, const float* __restrict__ v2,
    const float* __restrict__ v3, const float* __restrict__ v4, int sv4, float rk)
{
    extern __shared__ char smem[];
    const int bz = blockIdx.z;
    int KdL = Kd;
    int triL = tri;
    if (fuse) {
        if (bz == 4)      { Ah = A2h; Bh = B2h; Ch = C2h; KdL = Kd2; triL = 0; }
        else if (bz == 5) { Ah = A3h; Bh = B3h; Ch = C3h; KdL = Kd2; triL = 0; }
        else {
            Ah += (long)bz * sA;
            Bh += (long)bz * sB;
            Ch += (long)bz * sCb;
        }
    } else {
        Ah += (long)bz * sA;
        Bh += (long)bz * sB;
        if (Cf) Cf += (long)bz * sCf;
        if (Ch) Ch += (long)bz * sCb;
        if (v1) v1 += (long)bz * sv1;
        if (v4) v4 += (long)bz * sv4;
    }

    int m0, n0;
    if (triL) {
        if (blockIdx.x >= 36) return;
        int t = blockIdx.x, ti = 0;
        while (t >= 8 - ti) { t -= 8 - ti; ti++; }
        m0 = ti * 128;
        n0 = (ti + t) * 128;
    } else if (fuse) {
        m0 = (blockIdx.x >> 3) * 128;
        n0 = (blockIdx.x & 7) * 128;
    } else {
        m0 = blockIdx.y * 128;
        n0 = blockIdx.x * 128;
    }
    const int tid = threadIdx.x;
    const int lane = tid & 31;
    const int wid = tid >> 5;
    const int mw = (wid >> 2) * 32;
    const int nw = (wid & 3) * 32;
    const uint32_t sbase = smem_u32(smem);

    float acc[2][4][4];
#pragma unroll
    for (int mt = 0; mt < 2; mt++)
#pragma unroll
        for (int nf = 0; nf < 4; nf++)
#pragma unroll
            for (int q = 0; q < 4; q++) acc[mt][nf][q] = 0.f;

    const int nCh = KdL / 64;
    auto issue = [&](int c) {
        uint32_t sb = sbase + (uint32_t)(c & 3) * STAGE;
        long k0 = (long)c * 64;
        issue_tile(sb + OFF_A, Ah + (long)m0 * KdL + k0, KdL, tid);
        issue_tile(sb + OFF_B, Bh + (long)n0 * KdL + k0, KdL, tid);
        asm volatile("cp.async.commit_group;" ::: "memory");
    };

    issue(0); issue(1); issue(2);
    for (int c = 0; c < nCh; c++) {
        if (c + 3 <= nCh) {
            asm volatile("cp.async.wait_group 2;" ::: "memory");
        } else if (c + 2 == nCh) {
            asm volatile("cp.async.wait_group 1;" ::: "memory");
        } else {
            asm volatile("cp.async.wait_group 0;" ::: "memory");
        }
        __syncthreads();
        if (c + 3 < nCh) issue(c + 3);
        const uint32_t sb = sbase + (uint32_t)(c & 3) * STAGE;
        compute_ks(sb, 0, mw, nw, lane, acc);
        compute_ks(sb, 1, mw, nw, lane, acc);
        compute_ks(sb, 2, mw, nw, lane, acc);
        compute_ks(sb, 3, mw, nw, lane, acc);
    }
    __syncthreads();

    // epilogue
    const int r = lane >> 2;
    const int cp = (lane & 3) * 2;
#pragma unroll
    for (int mt = 0; mt < 2; mt++)
#pragma unroll
        for (int rr = 0; rr < 2; rr++) {
            const int m = m0 + mw + mt * 16 + r + rr * 8;
            float pv = 0.f, bkv = 0.f;
            if (mode == 1) { pv = v1[m]; bkv = v3[m]; }
#pragma unroll
            for (int nf = 0; nf < 4; nf++) {
                const int nloc = nf * 8 + cp;
                const int n = n0 + nw + nloc;
                float f0 = alpha * acc[mt][nf][rr * 2 + 0];
                float f1 = alpha * acc[mt][nf][rr * 2 + 1];
                if (mode == 1) {
                    f0 += pv * v2[n + 0] + bkv * (v4[n + 0] + rk * v2[n + 0]);
                    f1 += pv * v2[n + 1] + bkv * (v4[n + 1] + rk * v2[n + 1]);
                } else if (mode == 2) {
                    f0 += v1[n + 0];
                    f1 += v1[n + 1];
                }
                long co = (long)m * Nd + n;
                if (Cf) *(float2*)(Cf + co) = make_float2(f0, f1);
                if (Ch) *(uint32_t*)(Ch + co) = pack2(f0, f1);
            }
        }
}

// ===========================================================================
// Launch — single stream; fused preprocessing, merged G+P+Q GEMM.
// ===========================================================================
extern "C" void kernel_launch(void* const* d_in, const int* in_sizes, int n_in,
                              void* d_out, int out_size)
{
    const float* x  = (const float*)d_in[0];
    const float* Wq = (const float*)d_in[1];
    const float* bq = (const float*)d_in[2];
    const float* Wk = (const float*)d_in[3];
    const float* bk = (const float*)d_in[4];
    const float* Wv = (const float*)d_in[5];
    const float* bv = (const float*)d_in[6];
    const float* Wo = (const float*)d_in[7];
    const float* bo = (const float*)d_in[8];
    float* out = (float*)d_out;

    char* scr = nullptr;
    cudaGetSymbolAddress((void**)&scr, g_scratch);
    auto HF = [&](long off) { return (__half*)(scr + off); };

    __half *xs_h = HF(OFF_XS_H);
    __half *xt_h = HF(OFF_XT_H);
    __half *wqt_h = HF(OFF_WQT_H);
    __half *wkt_h = HF(OFF_WKT_H);
    __half *wvt_h = HF(OFF_WVT_H);
    __half *wo_h  = HF(OFF_WO_H);
    __half *P_h = HF(OFF_P_H);
    __half *Q_h = HF(OFF_Q_H);
    __half *G_h = HF(OFF_G_H);
    __half *R_h = HF(OFF_R_H);
    __half *UT_h = HF(OFF_UT_H);

    float* vec = (float*)(scr + OFF_VEC);
    float* s    = vec;                 // [B][E]
    float* p    = s    + Bd * Ed;
    float* r    = p    + Bd * Ed;
    float* u1   = r    + Bd * Ed;
    float* w2   = u1   + Bd * Ed;
    float* t2   = w2   + Bd * Ed;
    float* d    = t2   + Bd * Ed;
    float* cb   = d    + Bd * Ed;
    float* u2   = cb   + Bd * Ed;      // [E]
    float* w1   = u2   + Ed;
    float* t1   = w1   + Ed;
    float* dp   = t1   + Ed;           // [B]
    float* db   = dp   + Bd;           // [1]
    float* part_w  = db + 256;                 // [2][KSW][Ed]
    float* part_mv = part_w + 2 * KSW * Ed;    // [Bd][KS][Ed]
    float* part_cs = part_mv + Bd * KS * Ed;   // [Bd][CS][Ed]

    const long sX = (long)Sd * Ed;     // 2M elems
    const long sXT = (long)Ed * Sd;
    const long sEE = (long)Ed * Ed;

    cudaFuncSetAttribute(hf_gemm, cudaFuncAttributeMaxDynamicSharedMemorySize, DYN_SMEM);
    dim3 blk(512);

    // ---- preprocessing (3 launches; x and Wq/Wk read exactly once) ----
    xsplit_k<<<dim3(Ed / 32, Sd / 32, Bd), dim3(32, 8)>>>(x, sX, xs_h, sX, xt_h, sXT, part_cs);
    tsplitW_k<<<dim3(32, 32, 3), dim3(32, 8)>>>(Wq, Wk, Wv, bk, bq,
                                                wqt_h, wkt_h, wvt_h, part_w);
    split_wo_k<<<sEE / 4 / 256, 256>>>(Wo, wo_h, sEE / 4);

    // ---- vectors (4 launches) ----
    red1_k<<<dim3(Ed / 256, 6), 256>>>(part_w, part_cs, u2, t1, s);
    rowdot_prw_k<<<dim3(Ed / 8, Bd, 3), 256>>>(Wk, Wv, Wo, s, bv, p, r, w1);
    mv2_part_k<<<dim3(Ed / 256, KS, Bd), 256>>>(Wq, p, part_mv);
    red2_k<<<dim3(Ed / 8, Bd, 3), 256>>>(part_mv, Wo, r, p, bk, bq, u1, w2, dp, db);

    // ---- fused GEMM: z<4 -> G_b (tri, K=2048) ; z=4 -> P ; z=5 -> Q ----
    hf_gemm<<<dim3(64, 1, 6), blk, DYN_SMEM>>>(xt_h, sXT, xt_h, sXT,
        nullptr, 0, G_h, sEE, Ed, Sd, 1.f, 0, 1, 1,
        wqt_h, wkt_h, P_h,
        wo_h, wvt_h, Q_h, Ed,
        nullptr, 0, nullptr, nullptr, nullptr, 0, 0.f);
    mirror_k<<<dim3(Ed / 32, Ed / 32, Bd), dim3(32, 8)>>>(G_h, sEE);

    // cb chain (3 launches)
    rowdot_hf_k<<<dim3(Ed / 8, Bd), 256>>>(G_h, sEE, t1, t2, Ed);
    dfin_k<<<dim3(Ed / 8, Bd), 256>>>(Wv, t2, bv, r, dp, db, d);
    rowdot_k<<<dim3(Ed / 8, Bd), 256>>>(Wo, d, Ed, bo, cb, Ed, Ed, SCALE_F);

    // R_b = Q G_b (G symmetric -> row-major as B ok)
    hf_gemm<<<dim3(8, 8, Bd), blk, DYN_SMEM>>>(Q_h, 0, G_h, sEE,
        nullptr, 0, R_h, sEE, Ed, Ed, 1.f, 0, 0, 0,
        nullptr, nullptr, nullptr, nullptr, nullptr, nullptr, 0,
        nullptr, 0, nullptr, nullptr, nullptr, 0, 0.f);
    // UT_b = R_b P^T + w2 u2^T + w1 (u1 + S u2)^T
    hf_gemm<<<dim3(8, 8, Bd), blk, DYN_SMEM>>>(R_h, sEE, P_h, 0,
        nullptr, 0, UT_h, sEE, Ed, Ed, 1.f, 1, 0, 0,
        nullptr, nullptr, nullptr, nullptr, nullptr, nullptr, 0,
        w2, Ed, u2, w1, u1, Ed, (float)Sd);
    // out_b = SCALE * x UT^T + c_b
    hf_gemm<<<dim3(8, 16, Bd), blk, DYN_SMEM>>>(xs_h, sX, UT_h, sEE,
        out, sX, nullptr, 0, Ed, Ed, SCALE_F, 2, 0, 0,
        nullptr, nullptr, nullptr, nullptr, nullptr, nullptr, 0,
        cb, Ed, nullptr, nullptr, nullptr, 0, 0.f);
}